// round 1
// baseline (speedup 1.0000x reference)
#include <cuda_runtime.h>
#include <cuda_bf16.h>
#include <math.h>

// ---------------- problem constants (fixed shapes from setup_inputs) ----------------
constexpr int B_   = 16;
constexpr int MCLS = 4;
constexpr int NF   = 12;
constexpr int LF   = 196;
constexpr int E_   = 768;
constexpr int H_   = 12;
constexpr int D_   = 64;
constexpr int T_   = MCLS + NF * LF;   // 2356
constexpr int ROWS = B_ * T_;          // 37696
constexpr float SCALE = 0.125f;        // d^-0.5 = 1/8

// ---------------- scratch (device globals; no runtime allocation) ----------------
__device__ float g_q[(size_t)B_ * H_ * T_ * D_];     // (BH, T, 64)
__device__ float g_k[(size_t)B_ * H_ * T_ * D_];
__device__ float g_v[(size_t)B_ * H_ * T_ * D_];
__device__ float g_attn[(size_t)B_ * T_ * E_];       // (B, T, E)

// ---------------- fused QKV SGEMM: X(ROWS,768) @ W(768,768) + b ----------------
// gridDim = (6, 295, 3); z selects Q/K/V. Epilogue writes head-major layout.
#define BM 128
#define BN 128
#define BKK 16

__global__ __launch_bounds__(256) void sgemm_qkv_kernel(
    const float* __restrict__ X,
    const float* __restrict__ Wq, const float* __restrict__ bq,
    const float* __restrict__ Wk, const float* __restrict__ bk,
    const float* __restrict__ Wv, const float* __restrict__ bv)
{
    const float* W; const float* bias; float* out; float scale;
    int z = blockIdx.z;
    if (z == 0)      { W = Wq; bias = bq; out = g_q; scale = SCALE; }
    else if (z == 1) { W = Wk; bias = bk; out = g_k; scale = 1.0f;  }
    else             { W = Wv; bias = bv; out = g_v; scale = 1.0f;  }

    __shared__ float As[BKK][BM];
    __shared__ float Bs[BKK][BN];

    int tid  = threadIdx.x;
    int row0 = blockIdx.y * BM;
    int col0 = blockIdx.x * BN;
    int tr   = (tid / 16) * 8;
    int tc   = (tid % 16) * 8;

    float acc[8][8];
    #pragma unroll
    for (int i = 0; i < 8; i++)
        #pragma unroll
        for (int j = 0; j < 8; j++) acc[i][j] = 0.f;

    for (int k0 = 0; k0 < E_; k0 += BKK) {
        // load A tile (128x16), transposed into As[k][m]
        #pragma unroll
        for (int i = 0; i < 2; i++) {
            int f  = tid + i * 256;
            int ar = f >> 2;
            int ac = (f & 3) * 4;
            int grow = row0 + ar;
            float4 v = make_float4(0.f, 0.f, 0.f, 0.f);
            if (grow < ROWS)
                v = *(const float4*)&X[(size_t)grow * E_ + k0 + ac];
            As[ac + 0][ar] = v.x; As[ac + 1][ar] = v.y;
            As[ac + 2][ar] = v.z; As[ac + 3][ar] = v.w;
        }
        // load B tile (16x128)
        #pragma unroll
        for (int i = 0; i < 2; i++) {
            int f  = tid + i * 256;
            int br = f >> 5;
            int bc = (f & 31) * 4;
            *(float4*)&Bs[br][bc] = *(const float4*)&W[(size_t)(k0 + br) * E_ + col0 + bc];
        }
        __syncthreads();
        #pragma unroll
        for (int k = 0; k < BKK; k++) {
            float a[8], bb[8];
            #pragma unroll
            for (int i = 0; i < 8; i++) a[i]  = As[k][tr + i];
            #pragma unroll
            for (int j = 0; j < 8; j++) bb[j] = Bs[k][tc + j];
            #pragma unroll
            for (int i = 0; i < 8; i++)
                #pragma unroll
                for (int j = 0; j < 8; j++)
                    acc[i][j] += a[i] * bb[j];
        }
        __syncthreads();
    }

    // epilogue: (row, e) -> (bh, t, dd) head-major
    #pragma unroll
    for (int i = 0; i < 8; i++) {
        int grow = row0 + tr + i;
        if (grow >= ROWS) break;
        int b = grow / T_;
        int t = grow % T_;
        #pragma unroll
        for (int j = 0; j < 8; j++) {
            int e  = col0 + tc + j;
            float v = (acc[i][j] + bias[e]) * scale;
            int h  = e >> 6;
            int dd = e & 63;
            out[(((size_t)(b * H_ + h)) * T_ + t) * D_ + dd] = v;
        }
    }
}

// ---------------- output projection SGEMM: g_attn(ROWS,768) @ Wo + bo -> d_out ----------------
__global__ __launch_bounds__(256) void sgemm_out_kernel(
    const float* __restrict__ Wo, const float* __restrict__ bo,
    float* __restrict__ out)
{
    __shared__ float As[BKK][BM];
    __shared__ float Bs[BKK][BN];

    int tid  = threadIdx.x;
    int row0 = blockIdx.y * BM;
    int col0 = blockIdx.x * BN;
    int tr   = (tid / 16) * 8;
    int tc   = (tid % 16) * 8;

    float acc[8][8];
    #pragma unroll
    for (int i = 0; i < 8; i++)
        #pragma unroll
        for (int j = 0; j < 8; j++) acc[i][j] = 0.f;

    for (int k0 = 0; k0 < E_; k0 += BKK) {
        #pragma unroll
        for (int i = 0; i < 2; i++) {
            int f  = tid + i * 256;
            int ar = f >> 2;
            int ac = (f & 3) * 4;
            int grow = row0 + ar;
            float4 v = make_float4(0.f, 0.f, 0.f, 0.f);
            if (grow < ROWS)
                v = *(const float4*)&g_attn[(size_t)grow * E_ + k0 + ac];
            As[ac + 0][ar] = v.x; As[ac + 1][ar] = v.y;
            As[ac + 2][ar] = v.z; As[ac + 3][ar] = v.w;
        }
        #pragma unroll
        for (int i = 0; i < 2; i++) {
            int f  = tid + i * 256;
            int br = f >> 5;
            int bc = (f & 31) * 4;
            *(float4*)&Bs[br][bc] = *(const float4*)&Wo[(size_t)(k0 + br) * E_ + col0 + bc];
        }
        __syncthreads();
        #pragma unroll
        for (int k = 0; k < BKK; k++) {
            float a[8], bb[8];
            #pragma unroll
            for (int i = 0; i < 8; i++) a[i]  = As[k][tr + i];
            #pragma unroll
            for (int j = 0; j < 8; j++) bb[j] = Bs[k][tc + j];
            #pragma unroll
            for (int i = 0; i < 8; i++)
                #pragma unroll
                for (int j = 0; j < 8; j++)
                    acc[i][j] += a[i] * bb[j];
        }
        __syncthreads();
    }

    #pragma unroll
    for (int i = 0; i < 8; i++) {
        int grow = row0 + tr + i;
        if (grow >= ROWS) break;
        #pragma unroll
        for (int j = 0; j < 8; j++) {
            int e = col0 + tc + j;
            out[(size_t)grow * E_ + e] = acc[i][j] + bo[e];
        }
    }
}

// ---------------- frame attention: one block per (bh, window) ----------------
// 196 queries attend to [4 CLS keys + 196 local keys] = 200 keys. K,V in SMEM.
__global__ __launch_bounds__(256) void frame_attn_kernel()
{
    int bx = blockIdx.x;
    int bh = bx / NF;
    int n  = bx % NF;
    int b  = bh / H_;
    int h  = bh % H_;

    extern __shared__ float smem[];
    float* Ks = smem;            // 200*64
    float* Vs = smem + 200 * D_; // 200*64

    const float* kbase = g_k + (size_t)bh * T_ * D_;
    const float* vbase = g_v + (size_t)bh * T_ * D_;

    for (int idx = threadIdx.x; idx < 200 * 16; idx += 256) {
        int r  = idx / 16;
        int c4 = (idx % 16) * 4;
        int t  = (r < MCLS) ? r : (MCLS + n * LF + (r - MCLS));
        *(float4*)&Ks[r * D_ + c4] = *(const float4*)&kbase[(size_t)t * D_ + c4];
        *(float4*)&Vs[r * D_ + c4] = *(const float4*)&vbase[(size_t)t * D_ + c4];
    }
    __syncthreads();

    int l = threadIdx.x;
    if (l >= LF) return;
    int tq = MCLS + n * LF + l;

    const float* qrow = g_q + ((size_t)bh * T_ + tq) * D_;
    float4 q[16];
    #pragma unroll
    for (int i = 0; i < 16; i++) q[i] = *(const float4*)&qrow[i * 4];

    float m = -1e30f, lsum = 0.f;
    float4 acc[16];
    #pragma unroll
    for (int i = 0; i < 16; i++) acc[i] = make_float4(0.f, 0.f, 0.f, 0.f);

    for (int kk = 0; kk < 200; kk++) {
        const float* kr = &Ks[kk * D_];
        float s = 0.f;
        #pragma unroll
        for (int i = 0; i < 16; i++) {
            float4 kv = *(const float4*)&kr[i * 4];
            s += q[i].x * kv.x + q[i].y * kv.y + q[i].z * kv.z + q[i].w * kv.w;
        }
        float mnew = fmaxf(m, s);
        if (mnew != m) {
            float corr = __expf(m - mnew);
            lsum *= corr;
            #pragma unroll
            for (int i = 0; i < 16; i++) {
                acc[i].x *= corr; acc[i].y *= corr;
                acc[i].z *= corr; acc[i].w *= corr;
            }
            m = mnew;
        }
        float p = __expf(s - m);
        lsum += p;
        const float* vr = &Vs[kk * D_];
        #pragma unroll
        for (int i = 0; i < 16; i++) {
            float4 vv = *(const float4*)&vr[i * 4];
            acc[i].x += p * vv.x; acc[i].y += p * vv.y;
            acc[i].z += p * vv.z; acc[i].w += p * vv.w;
        }
    }

    float inv = 1.f / lsum;
    float* dst = g_attn + ((size_t)(b * T_ + tq)) * E_ + h * D_;
    #pragma unroll
    for (int i = 0; i < 16; i++) {
        float4 o = make_float4(acc[i].x * inv, acc[i].y * inv,
                               acc[i].z * inv, acc[i].w * inv);
        *(float4*)&dst[i * 4] = o;
    }
}

// ---------------- CLS attention: one block per bh, one warp per query ----------------
__global__ __launch_bounds__(128) void cls_attn_kernel()
{
    int bh   = blockIdx.x;
    int b    = bh / H_;
    int h    = bh % H_;
    int warp = threadIdx.x / 32;
    int lane = threadIdx.x % 32;

    const float* qrow = g_q + ((size_t)bh * T_ + warp) * D_;
    float4 q[16];
    #pragma unroll
    for (int i = 0; i < 16; i++) q[i] = *(const float4*)&qrow[i * 4];

    const float* kbase = g_k + (size_t)bh * T_ * D_;
    const float* vbase = g_v + (size_t)bh * T_ * D_;

    float m = -1e30f, lsum = 0.f;
    float4 acc[16];
    #pragma unroll
    for (int i = 0; i < 16; i++) acc[i] = make_float4(0.f, 0.f, 0.f, 0.f);

    for (int t = lane; t < T_; t += 32) {
        const float* kr = kbase + (size_t)t * D_;
        float s = 0.f;
        #pragma unroll
        for (int i = 0; i < 16; i++) {
            float4 kv = *(const float4*)&kr[i * 4];
            s += q[i].x * kv.x + q[i].y * kv.y + q[i].z * kv.z + q[i].w * kv.w;
        }
        float mnew = fmaxf(m, s);
        if (mnew != m) {
            float corr = __expf(m - mnew);
            lsum *= corr;
            #pragma unroll
            for (int i = 0; i < 16; i++) {
                acc[i].x *= corr; acc[i].y *= corr;
                acc[i].z *= corr; acc[i].w *= corr;
            }
            m = mnew;
        }
        float p = __expf(s - m);
        lsum += p;
        const float* vr = vbase + (size_t)t * D_;
        #pragma unroll
        for (int i = 0; i < 16; i++) {
            float4 vv = *(const float4*)&vr[i * 4];
            acc[i].x += p * vv.x; acc[i].y += p * vv.y;
            acc[i].z += p * vv.z; acc[i].w += p * vv.w;
        }
    }

    // merge online-softmax state across lanes (butterfly)
    #pragma unroll
    for (int off = 16; off > 0; off >>= 1) {
        float m2 = __shfl_xor_sync(0xFFFFFFFFu, m, off);
        float l2 = __shfl_xor_sync(0xFFFFFFFFu, lsum, off);
        float mn = fmaxf(m, m2);
        float c1 = __expf(m - mn);
        float c2 = __expf(m2 - mn);
        lsum = lsum * c1 + l2 * c2;
        #pragma unroll
        for (int i = 0; i < 16; i++) {
            acc[i].x = acc[i].x * c1 + __shfl_xor_sync(0xFFFFFFFFu, acc[i].x, off) * c2;
            acc[i].y = acc[i].y * c1 + __shfl_xor_sync(0xFFFFFFFFu, acc[i].y, off) * c2;
            acc[i].z = acc[i].z * c1 + __shfl_xor_sync(0xFFFFFFFFu, acc[i].z, off) * c2;
            acc[i].w = acc[i].w * c1 + __shfl_xor_sync(0xFFFFFFFFu, acc[i].w, off) * c2;
        }
        m = mn;
    }

    float inv = 1.f / lsum;
    float* dst = g_attn + ((size_t)(b * T_ + warp)) * E_ + h * D_;
    if (lane < 16) {
        float4 o = make_float4(acc[lane].x * inv, acc[lane].y * inv,
                               acc[lane].z * inv, acc[lane].w * inv);
        *(float4*)&dst[lane * 4] = o;
    }
}

// ---------------- launch ----------------
extern "C" void kernel_launch(void* const* d_in, const int* in_sizes, int n_in,
                              void* d_out, int out_size)
{
    const float* hidden = (const float*)d_in[0];
    const float* Wq = (const float*)d_in[1];
    const float* bq = (const float*)d_in[2];
    const float* Wk = (const float*)d_in[3];
    const float* bk = (const float*)d_in[4];
    const float* Wv = (const float*)d_in[5];
    const float* bv = (const float*)d_in[6];
    const float* Wo = (const float*)d_in[7];
    const float* bo = (const float*)d_in[8];
    float* out = (float*)d_out;

    const int smem_attn = 2 * 200 * D_ * (int)sizeof(float); // 102400 B
    cudaFuncSetAttribute(frame_attn_kernel,
                         cudaFuncAttributeMaxDynamicSharedMemorySize, smem_attn);

    dim3 g1(E_ / BN, (ROWS + BM - 1) / BM, 3);
    sgemm_qkv_kernel<<<g1, 256>>>(hidden, Wq, bq, Wk, bk, Wv, bv);

    frame_attn_kernel<<<B_ * H_ * NF, 256, smem_attn>>>();
    cls_attn_kernel<<<B_ * H_, 128>>>();

    dim3 g2(E_ / BN, (ROWS + BM - 1) / BM, 1);
    sgemm_out_kernel<<<g2, 256>>>(Wo, bo, out);
}

// round 2
// speedup vs baseline: 2.0887x; 2.0887x over previous
#include <cuda_runtime.h>
#include <cuda_bf16.h>
#include <math.h>

// ---------------- problem constants ----------------
constexpr int B_   = 16;
constexpr int MCLS = 4;
constexpr int NF   = 12;
constexpr int LF   = 196;
constexpr int E_   = 768;
constexpr int H_   = 12;
constexpr int D_   = 64;
constexpr int T_   = MCLS + NF * LF;   // 2356
constexpr int ROWS = B_ * T_;          // 37696
constexpr float SCALE = 0.125f;

// ---------------- scratch ----------------
__device__ float g_q[(size_t)B_ * H_ * T_ * D_];
__device__ float g_k[(size_t)B_ * H_ * T_ * D_];
__device__ float g_v[(size_t)B_ * H_ * T_ * D_];
__device__ float g_attn[(size_t)B_ * T_ * E_];

// ---------------- tf32 MMA GEMM config ----------------
constexpr int BM = 128;
constexpr int BN = 128;
constexpr int BKt = 32;
constexpr int AS_STRIDE = 36;    // 36 % 32 == 4 -> conflict-free A fragment loads
constexpr int BS_STRIDE = 136;   // 136 % 32 == 8 -> conflict-free B fragment loads
constexpr int AS_SIZE = BM * AS_STRIDE;  // 4608 floats
constexpr int BS_SIZE = BKt * BS_STRIDE; // 4352 floats
constexpr int SMEM_BYTES = 2 * (AS_SIZE + BS_SIZE) * 4;  // 71680 B
constexpr int KTILES = E_ / BKt;  // 24

__device__ __forceinline__ void cp16(float* dst, const float* src, int srcsize) {
    unsigned s = (unsigned)__cvta_generic_to_shared(dst);
    asm volatile("cp.async.cg.shared.global [%0], [%1], 16, %2;\n"
                 :: "r"(s), "l"(src), "r"(srcsize));
}
__device__ __forceinline__ unsigned f2tf32(float x) {
    unsigned u;
    asm("cvt.rna.tf32.f32 %0, %1;" : "=r"(u) : "f"(x));
    return u;
}
__device__ __forceinline__ void mma_tf32(float c[4], const unsigned a[4], const unsigned b[2]) {
    asm volatile(
        "mma.sync.aligned.m16n8k8.row.col.f32.tf32.tf32.f32 "
        "{%0,%1,%2,%3},{%4,%5,%6,%7},{%8,%9},{%0,%1,%2,%3};\n"
        : "+f"(c[0]), "+f"(c[1]), "+f"(c[2]), "+f"(c[3])
        : "r"(a[0]), "r"(a[1]), "r"(a[2]), "r"(a[3]), "r"(b[0]), "r"(b[1]));
}

__device__ __forceinline__ void load_tile(
    const float* __restrict__ X, const float* __restrict__ W,
    float* As, float* Bs, int row0, int col0, int kt, int tid)
{
    int k0 = kt * BKt;
    #pragma unroll
    for (int i = 0; i < 4; i++) {
        int f  = tid + i * 256;
        int ar = f >> 3;
        int ac = (f & 7) * 4;
        int grow = row0 + ar;
        bool v = grow < ROWS;
        const float* src = X + (size_t)(v ? grow : 0) * E_ + k0 + ac;
        cp16(As + ar * AS_STRIDE + ac, src, v ? 16 : 0);
    }
    #pragma unroll
    for (int i = 0; i < 4; i++) {
        int f  = tid + i * 256;
        int br = f >> 5;
        int bc = (f & 31) * 4;
        cp16(Bs + br * BS_STRIDE + bc, W + (size_t)(k0 + br) * E_ + col0 + bc, 16);
    }
}

__device__ __forceinline__ void compute_tile(
    const float* As, const float* Bs,
    int warp_m, int warp_n, int lane, float acc[2][8][4])
{
    #pragma unroll
    for (int kk = 0; kk < BKt; kk += 8) {
        unsigned a[2][4], b[8][2];
        int cb = kk + (lane & 3);
        int g  = lane >> 2;
        #pragma unroll
        for (int mt = 0; mt < 2; mt++) {
            const float* p = As + (warp_m + mt * 16 + g) * AS_STRIDE + cb;
            a[mt][0] = f2tf32(p[0]);
            a[mt][1] = f2tf32(p[8 * AS_STRIDE]);
            a[mt][2] = f2tf32(p[4]);
            a[mt][3] = f2tf32(p[8 * AS_STRIDE + 4]);
        }
        const float* q = Bs + cb * BS_STRIDE + warp_n + g;
        #pragma unroll
        for (int nt = 0; nt < 8; nt++) {
            b[nt][0] = f2tf32(q[nt * 8]);
            b[nt][1] = f2tf32(q[4 * BS_STRIDE + nt * 8]);
        }
        #pragma unroll
        for (int mt = 0; mt < 2; mt++)
            #pragma unroll
            for (int nt = 0; nt < 8; nt++)
                mma_tf32(acc[mt][nt], a[mt], b[nt]);
    }
}

__device__ __forceinline__ void gemm_main(
    const float* __restrict__ X, const float* __restrict__ W,
    int row0, int col0, float acc[2][8][4], float* smem)
{
    float* As0 = smem;
    float* As1 = smem + AS_SIZE;
    float* Bs0 = smem + 2 * AS_SIZE;
    float* Bs1 = Bs0 + BS_SIZE;

    int tid  = threadIdx.x;
    int lane = tid & 31;
    int wid  = tid >> 5;
    int warp_m = (wid >> 1) * 32;
    int warp_n = (wid & 1) * 64;

    load_tile(X, W, As0, Bs0, row0, col0, 0, tid);
    asm volatile("cp.async.commit_group;\n" ::: "memory");

    for (int kt = 0; kt < KTILES; kt++) {
        float* Ac = (kt & 1) ? As1 : As0;
        float* Bc = (kt & 1) ? Bs1 : Bs0;
        if (kt + 1 < KTILES) {
            float* An = (kt & 1) ? As0 : As1;
            float* Bn = (kt & 1) ? Bs0 : Bs1;
            load_tile(X, W, An, Bn, row0, col0, kt + 1, tid);
            asm volatile("cp.async.commit_group;\n" ::: "memory");
            asm volatile("cp.async.wait_group 1;\n" ::: "memory");
        } else {
            asm volatile("cp.async.wait_group 0;\n" ::: "memory");
        }
        __syncthreads();
        compute_tile(Ac, Bc, warp_m, warp_n, lane, acc);
        __syncthreads();
    }
}

// ---------------- QKV GEMM (z selects Q/K/V), head-major epilogue ----------------
__global__ __launch_bounds__(256) void tf32_gemm_qkv(
    const float* __restrict__ X,
    const float* __restrict__ Wq, const float* __restrict__ bq,
    const float* __restrict__ Wk, const float* __restrict__ bk,
    const float* __restrict__ Wv, const float* __restrict__ bv)
{
    extern __shared__ float smem[];
    const float* W; const float* bias; float* out; float scale;
    int z = blockIdx.z;
    if (z == 0)      { W = Wq; bias = bq; out = g_q; scale = SCALE; }
    else if (z == 1) { W = Wk; bias = bk; out = g_k; scale = 1.0f;  }
    else             { W = Wv; bias = bv; out = g_v; scale = 1.0f;  }

    int row0 = blockIdx.y * BM;
    int col0 = blockIdx.x * BN;

    float acc[2][8][4];
    #pragma unroll
    for (int mt = 0; mt < 2; mt++)
        #pragma unroll
        for (int nt = 0; nt < 8; nt++)
            #pragma unroll
            for (int i = 0; i < 4; i++) acc[mt][nt][i] = 0.f;

    gemm_main(X, W, row0, col0, acc, smem);

    int lane = threadIdx.x & 31;
    int wid  = threadIdx.x >> 5;
    int warp_m = (wid >> 1) * 32;
    int warp_n = (wid & 1) * 64;

    #pragma unroll
    for (int mt = 0; mt < 2; mt++) {
        #pragma unroll
        for (int nt = 0; nt < 8; nt++) {
            int coln = warp_n + nt * 8 + (lane & 3) * 2;
            int e  = col0 + coln;
            int h  = e >> 6;
            int dd = e & 63;
            float bv0 = bias[e];
            float bv1 = bias[e + 1];
            #pragma unroll
            for (int half = 0; half < 2; half++) {
                int r = warp_m + mt * 16 + (lane >> 2) + half * 8;
                int grow = row0 + r;
                if (grow < ROWS) {
                    int bb = grow / T_;
                    int t  = grow % T_;
                    float2 val;
                    val.x = (acc[mt][nt][half * 2 + 0] + bv0) * scale;
                    val.y = (acc[mt][nt][half * 2 + 1] + bv1) * scale;
                    *(float2*)&out[(((size_t)(bb * H_ + h)) * T_ + t) * D_ + dd] = val;
                }
            }
        }
    }
}

// ---------------- output projection GEMM ----------------
__global__ __launch_bounds__(256) void tf32_gemm_out(
    const float* __restrict__ Wo, const float* __restrict__ bo,
    float* __restrict__ out)
{
    extern __shared__ float smem[];
    int row0 = blockIdx.y * BM;
    int col0 = blockIdx.x * BN;

    float acc[2][8][4];
    #pragma unroll
    for (int mt = 0; mt < 2; mt++)
        #pragma unroll
        for (int nt = 0; nt < 8; nt++)
            #pragma unroll
            for (int i = 0; i < 4; i++) acc[mt][nt][i] = 0.f;

    gemm_main(g_attn, Wo, row0, col0, acc, smem);

    int lane = threadIdx.x & 31;
    int wid  = threadIdx.x >> 5;
    int warp_m = (wid >> 1) * 32;
    int warp_n = (wid & 1) * 64;

    #pragma unroll
    for (int mt = 0; mt < 2; mt++) {
        #pragma unroll
        for (int nt = 0; nt < 8; nt++) {
            int coln = warp_n + nt * 8 + (lane & 3) * 2;
            int e = col0 + coln;
            float bv0 = bo[e];
            float bv1 = bo[e + 1];
            #pragma unroll
            for (int half = 0; half < 2; half++) {
                int r = warp_m + mt * 16 + (lane >> 2) + half * 8;
                int grow = row0 + r;
                if (grow < ROWS) {
                    float2 val;
                    val.x = acc[mt][nt][half * 2 + 0] + bv0;
                    val.y = acc[mt][nt][half * 2 + 1] + bv1;
                    *(float2*)&out[(size_t)grow * E_ + e] = val;
                }
            }
        }
    }
}

// ---------------- frame attention (unchanged) ----------------
__global__ __launch_bounds__(256) void frame_attn_kernel()
{
    int bx = blockIdx.x;
    int bh = bx / NF;
    int n  = bx % NF;
    int b  = bh / H_;
    int h  = bh % H_;

    extern __shared__ float smem[];
    float* Ks = smem;
    float* Vs = smem + 200 * D_;

    const float* kbase = g_k + (size_t)bh * T_ * D_;
    const float* vbase = g_v + (size_t)bh * T_ * D_;

    for (int idx = threadIdx.x; idx < 200 * 16; idx += 256) {
        int r  = idx / 16;
        int c4 = (idx % 16) * 4;
        int t  = (r < MCLS) ? r : (MCLS + n * LF + (r - MCLS));
        *(float4*)&Ks[r * D_ + c4] = *(const float4*)&kbase[(size_t)t * D_ + c4];
        *(float4*)&Vs[r * D_ + c4] = *(const float4*)&vbase[(size_t)t * D_ + c4];
    }
    __syncthreads();

    int l = threadIdx.x;
    if (l >= LF) return;
    int tq = MCLS + n * LF + l;

    const float* qrow = g_q + ((size_t)bh * T_ + tq) * D_;
    float4 q[16];
    #pragma unroll
    for (int i = 0; i < 16; i++) q[i] = *(const float4*)&qrow[i * 4];

    float m = -1e30f, lsum = 0.f;
    float4 acc[16];
    #pragma unroll
    for (int i = 0; i < 16; i++) acc[i] = make_float4(0.f, 0.f, 0.f, 0.f);

    for (int kk = 0; kk < 200; kk++) {
        const float* kr = &Ks[kk * D_];
        float s = 0.f;
        #pragma unroll
        for (int i = 0; i < 16; i++) {
            float4 kv = *(const float4*)&kr[i * 4];
            s += q[i].x * kv.x + q[i].y * kv.y + q[i].z * kv.z + q[i].w * kv.w;
        }
        float mnew = fmaxf(m, s);
        if (mnew != m) {
            float corr = __expf(m - mnew);
            lsum *= corr;
            #pragma unroll
            for (int i = 0; i < 16; i++) {
                acc[i].x *= corr; acc[i].y *= corr;
                acc[i].z *= corr; acc[i].w *= corr;
            }
            m = mnew;
        }
        float p = __expf(s - m);
        lsum += p;
        const float* vr = &Vs[kk * D_];
        #pragma unroll
        for (int i = 0; i < 16; i++) {
            float4 vv = *(const float4*)&vr[i * 4];
            acc[i].x += p * vv.x; acc[i].y += p * vv.y;
            acc[i].z += p * vv.z; acc[i].w += p * vv.w;
        }
    }

    float inv = 1.f / lsum;
    float* dst = g_attn + ((size_t)(b * T_ + tq)) * E_ + h * D_;
    #pragma unroll
    for (int i = 0; i < 16; i++) {
        float4 o = make_float4(acc[i].x * inv, acc[i].y * inv,
                               acc[i].z * inv, acc[i].w * inv);
        *(float4*)&dst[i * 4] = o;
    }
}

// ---------------- CLS attention (unchanged) ----------------
__global__ __launch_bounds__(128) void cls_attn_kernel()
{
    int bh   = blockIdx.x;
    int b    = bh / H_;
    int h    = bh % H_;
    int warp = threadIdx.x / 32;
    int lane = threadIdx.x % 32;

    const float* qrow = g_q + ((size_t)bh * T_ + warp) * D_;
    float4 q[16];
    #pragma unroll
    for (int i = 0; i < 16; i++) q[i] = *(const float4*)&qrow[i * 4];

    const float* kbase = g_k + (size_t)bh * T_ * D_;
    const float* vbase = g_v + (size_t)bh * T_ * D_;

    float m = -1e30f, lsum = 0.f;
    float4 acc[16];
    #pragma unroll
    for (int i = 0; i < 16; i++) acc[i] = make_float4(0.f, 0.f, 0.f, 0.f);

    for (int t = lane; t < T_; t += 32) {
        const float* kr = kbase + (size_t)t * D_;
        float s = 0.f;
        #pragma unroll
        for (int i = 0; i < 16; i++) {
            float4 kv = *(const float4*)&kr[i * 4];
            s += q[i].x * kv.x + q[i].y * kv.y + q[i].z * kv.z + q[i].w * kv.w;
        }
        float mnew = fmaxf(m, s);
        if (mnew != m) {
            float corr = __expf(m - mnew);
            lsum *= corr;
            #pragma unroll
            for (int i = 0; i < 16; i++) {
                acc[i].x *= corr; acc[i].y *= corr;
                acc[i].z *= corr; acc[i].w *= corr;
            }
            m = mnew;
        }
        float p = __expf(s - m);
        lsum += p;
        const float* vr = vbase + (size_t)t * D_;
        #pragma unroll
        for (int i = 0; i < 16; i++) {
            float4 vv = *(const float4*)&vr[i * 4];
            acc[i].x += p * vv.x; acc[i].y += p * vv.y;
            acc[i].z += p * vv.z; acc[i].w += p * vv.w;
        }
    }

    #pragma unroll
    for (int off = 16; off > 0; off >>= 1) {
        float m2 = __shfl_xor_sync(0xFFFFFFFFu, m, off);
        float l2 = __shfl_xor_sync(0xFFFFFFFFu, lsum, off);
        float mn = fmaxf(m, m2);
        float c1 = __expf(m - mn);
        float c2 = __expf(m2 - mn);
        lsum = lsum * c1 + l2 * c2;
        #pragma unroll
        for (int i = 0; i < 16; i++) {
            acc[i].x = acc[i].x * c1 + __shfl_xor_sync(0xFFFFFFFFu, acc[i].x, off) * c2;
            acc[i].y = acc[i].y * c1 + __shfl_xor_sync(0xFFFFFFFFu, acc[i].y, off) * c2;
            acc[i].z = acc[i].z * c1 + __shfl_xor_sync(0xFFFFFFFFu, acc[i].z, off) * c2;
            acc[i].w = acc[i].w * c1 + __shfl_xor_sync(0xFFFFFFFFu, acc[i].w, off) * c2;
        }
        m = mn;
    }

    float inv = 1.f / lsum;
    float* dst = g_attn + ((size_t)(b * T_ + warp)) * E_ + h * D_;
    if (lane < 16) {
        float4 o = make_float4(acc[lane].x * inv, acc[lane].y * inv,
                               acc[lane].z * inv, acc[lane].w * inv);
        *(float4*)&dst[lane * 4] = o;
    }
}

// ---------------- launch ----------------
extern "C" void kernel_launch(void* const* d_in, const int* in_sizes, int n_in,
                              void* d_out, int out_size)
{
    const float* hidden = (const float*)d_in[0];
    const float* Wq = (const float*)d_in[1];
    const float* bq = (const float*)d_in[2];
    const float* Wk = (const float*)d_in[3];
    const float* bk = (const float*)d_in[4];
    const float* Wv = (const float*)d_in[5];
    const float* bv = (const float*)d_in[6];
    const float* Wo = (const float*)d_in[7];
    const float* bo = (const float*)d_in[8];
    float* out = (float*)d_out;

    cudaFuncSetAttribute(tf32_gemm_qkv,
                         cudaFuncAttributeMaxDynamicSharedMemorySize, SMEM_BYTES);
    cudaFuncSetAttribute(tf32_gemm_out,
                         cudaFuncAttributeMaxDynamicSharedMemorySize, SMEM_BYTES);
    const int smem_attn = 2 * 200 * D_ * (int)sizeof(float);
    cudaFuncSetAttribute(frame_attn_kernel,
                         cudaFuncAttributeMaxDynamicSharedMemorySize, smem_attn);

    dim3 g1(E_ / BN, (ROWS + BM - 1) / BM, 3);
    tf32_gemm_qkv<<<g1, 256, SMEM_BYTES>>>(hidden, Wq, bq, Wk, bk, Wv, bv);

    frame_attn_kernel<<<B_ * H_ * NF, 256, smem_attn>>>();
    cls_attn_kernel<<<B_ * H_, 128>>>();

    dim3 g2(E_ / BN, (ROWS + BM - 1) / BM, 1);
    tf32_gemm_out<<<g2, 256, SMEM_BYTES>>>(Wo, bo, out);
}

// round 4
// speedup vs baseline: 2.1416x; 1.0253x over previous
#include <cuda_runtime.h>
#include <cuda_bf16.h>
#include <math.h>

// ---------------- problem constants ----------------
constexpr int B_   = 16;
constexpr int MCLS = 4;
constexpr int NF   = 12;
constexpr int LF   = 196;
constexpr int E_   = 768;
constexpr int H_   = 12;
constexpr int D_   = 64;
constexpr int T_   = MCLS + NF * LF;   // 2356
constexpr int ROWS = B_ * T_;          // 37696
constexpr float SCALE = 0.125f;
constexpr int WELEMS = E_ * E_;        // 589824

// ---------------- scratch ----------------
__device__ float g_q[(size_t)B_ * H_ * T_ * D_];
__device__ float g_k[(size_t)B_ * H_ * T_ * D_];
__device__ float g_v[(size_t)B_ * H_ * T_ * D_];
__device__ float g_attn[(size_t)B_ * T_ * E_];   // written pre-rounded to tf32
__device__ float g_x[(size_t)ROWS * E_];         // hidden, pre-rounded to tf32
__device__ float g_w[(size_t)4 * WELEMS];        // Wq,Wk,Wv,Wo pre-rounded

__device__ __forceinline__ float round_tf32(float x) {
    unsigned u;
    asm("cvt.rna.tf32.f32 %0, %1;" : "=r"(u) : "f"(x));
    return __uint_as_float(u);
}

// ---------------- prep: round inputs/weights to tf32 once ----------------
__global__ __launch_bounds__(256) void prep_x_kernel(const float* __restrict__ X) {
    size_t i = ((size_t)blockIdx.x * 256 + threadIdx.x) * 4;
    if (i >= (size_t)ROWS * E_) return;
    float4 v = *(const float4*)&X[i];
    v.x = round_tf32(v.x); v.y = round_tf32(v.y);
    v.z = round_tf32(v.z); v.w = round_tf32(v.w);
    *(float4*)&g_x[i] = v;
}
__global__ __launch_bounds__(256) void prep_w_kernel(
    const float* __restrict__ Wq, const float* __restrict__ Wk,
    const float* __restrict__ Wv, const float* __restrict__ Wo) {
    size_t i = ((size_t)blockIdx.x * 256 + threadIdx.x) * 4;
    if (i >= (size_t)4 * WELEMS) return;
    int sel = (int)(i / WELEMS);
    size_t off = i - (size_t)sel * WELEMS;
    const float* W = (sel == 0) ? Wq : (sel == 1) ? Wk : (sel == 2) ? Wv : Wo;
    float4 v = *(const float4*)&W[off];
    v.x = round_tf32(v.x); v.y = round_tf32(v.y);
    v.z = round_tf32(v.z); v.w = round_tf32(v.w);
    *(float4*)&g_w[i] = v;
}

// ---------------- tf32 MMA GEMM config ----------------
constexpr int BM = 128;
constexpr int BN = 128;
constexpr int BKt = 32;
constexpr int AS_STRIDE = 36;
constexpr int BS_STRIDE = 136;
constexpr int AS_SIZE = BM * AS_STRIDE;
constexpr int BS_SIZE = BKt * BS_STRIDE;
constexpr int SMEM_BYTES = 2 * (AS_SIZE + BS_SIZE) * 4;  // 71680 B
constexpr int KTILES = E_ / BKt;

__device__ __forceinline__ void cp16(float* dst, const float* src, int srcsize) {
    unsigned s = (unsigned)__cvta_generic_to_shared(dst);
    asm volatile("cp.async.cg.shared.global [%0], [%1], 16, %2;\n"
                 :: "r"(s), "l"(src), "r"(srcsize));
}
__device__ __forceinline__ void mma_tf32(float c[4], const unsigned a[4], const unsigned b[2]) {
    asm volatile(
        "mma.sync.aligned.m16n8k8.row.col.f32.tf32.tf32.f32 "
        "{%0,%1,%2,%3},{%4,%5,%6,%7},{%8,%9},{%0,%1,%2,%3};\n"
        : "+f"(c[0]), "+f"(c[1]), "+f"(c[2]), "+f"(c[3])
        : "r"(a[0]), "r"(a[1]), "r"(a[2]), "r"(a[3]), "r"(b[0]), "r"(b[1]));
}

__device__ __forceinline__ void load_tile(
    const float* __restrict__ X, const float* __restrict__ W,
    float* As, float* Bs, int row0, int col0, int kt, int tid)
{
    int k0 = kt * BKt;
    #pragma unroll
    for (int i = 0; i < 4; i++) {
        int f  = tid + i * 256;
        int ar = f >> 3;
        int ac = (f & 7) * 4;
        int grow = row0 + ar;
        bool v = grow < ROWS;
        const float* src = X + (size_t)(v ? grow : 0) * E_ + k0 + ac;
        cp16(As + ar * AS_STRIDE + ac, src, v ? 16 : 0);
    }
    #pragma unroll
    for (int i = 0; i < 4; i++) {
        int f  = tid + i * 256;
        int br = f >> 5;
        int bc = (f & 31) * 4;
        cp16(Bs + br * BS_STRIDE + bc, W + (size_t)(k0 + br) * E_ + col0 + bc, 16);
    }
}

__device__ __forceinline__ void compute_tile(
    const float* As, const float* Bs,
    int warp_m, int warp_n, int lane, float acc[2][8][4])
{
    #pragma unroll
    for (int kk = 0; kk < BKt; kk += 8) {
        unsigned a[2][4], b[8][2];
        int cb = kk + (lane & 3);
        int g  = lane >> 2;
        #pragma unroll
        for (int mt = 0; mt < 2; mt++) {
            const unsigned* p = (const unsigned*)(As + (warp_m + mt * 16 + g) * AS_STRIDE + cb);
            a[mt][0] = p[0];
            a[mt][1] = p[8 * AS_STRIDE];
            a[mt][2] = p[4];
            a[mt][3] = p[8 * AS_STRIDE + 4];
        }
        const unsigned* q = (const unsigned*)(Bs + cb * BS_STRIDE + warp_n + g);
        #pragma unroll
        for (int nt = 0; nt < 8; nt++) {
            b[nt][0] = q[nt * 8];
            b[nt][1] = q[4 * BS_STRIDE + nt * 8];
        }
        #pragma unroll
        for (int mt = 0; mt < 2; mt++)
            #pragma unroll
            for (int nt = 0; nt < 8; nt++)
                mma_tf32(acc[mt][nt], a[mt], b[nt]);
    }
}

__device__ __forceinline__ void gemm_main(
    const float* __restrict__ X, const float* __restrict__ W,
    int row0, int col0, float acc[2][8][4], float* smem)
{
    float* As0 = smem;
    float* As1 = smem + AS_SIZE;
    float* Bs0 = smem + 2 * AS_SIZE;
    float* Bs1 = Bs0 + BS_SIZE;

    int tid  = threadIdx.x;
    int lane = tid & 31;
    int wid  = tid >> 5;
    int warp_m = (wid >> 1) * 32;
    int warp_n = (wid & 1) * 64;

    load_tile(X, W, As0, Bs0, row0, col0, 0, tid);
    asm volatile("cp.async.commit_group;\n" ::: "memory");

    for (int kt = 0; kt < KTILES; kt++) {
        float* Ac = (kt & 1) ? As1 : As0;
        float* Bc = (kt & 1) ? Bs1 : Bs0;
        if (kt + 1 < KTILES) {
            float* An = (kt & 1) ? As0 : As1;
            float* Bn = (kt & 1) ? Bs0 : Bs1;
            load_tile(X, W, An, Bn, row0, col0, kt + 1, tid);
            asm volatile("cp.async.commit_group;\n" ::: "memory");
            asm volatile("cp.async.wait_group 1;\n" ::: "memory");
        } else {
            asm volatile("cp.async.wait_group 0;\n" ::: "memory");
        }
        __syncthreads();
        compute_tile(Ac, Bc, warp_m, warp_n, lane, acc);
        __syncthreads();
    }
}

// ---------------- QKV GEMM ----------------
__global__ __launch_bounds__(256, 2) void tf32_gemm_qkv(
    const float* __restrict__ bq, const float* __restrict__ bk,
    const float* __restrict__ bv)
{
    extern __shared__ float smem[];
    int z = blockIdx.z;
    const float* W = g_w + (size_t)z * WELEMS;
    const float* bias = (z == 0) ? bq : (z == 1) ? bk : bv;
    float* out = (z == 0) ? g_q : (z == 1) ? g_k : g_v;
    float scale = (z == 0) ? SCALE : 1.0f;

    int row0 = blockIdx.y * BM;
    int col0 = blockIdx.x * BN;

    float acc[2][8][4];
    #pragma unroll
    for (int mt = 0; mt < 2; mt++)
        #pragma unroll
        for (int nt = 0; nt < 8; nt++)
            #pragma unroll
            for (int i = 0; i < 4; i++) acc[mt][nt][i] = 0.f;

    gemm_main(g_x, W, row0, col0, acc, smem);

    int lane = threadIdx.x & 31;
    int wid  = threadIdx.x >> 5;
    int warp_m = (wid >> 1) * 32;
    int warp_n = (wid & 1) * 64;

    #pragma unroll
    for (int mt = 0; mt < 2; mt++) {
        #pragma unroll
        for (int nt = 0; nt < 8; nt++) {
            int coln = warp_n + nt * 8 + (lane & 3) * 2;
            int e  = col0 + coln;
            int h  = e >> 6;
            int dd = e & 63;
            float bv0 = bias[e];
            float bv1 = bias[e + 1];
            #pragma unroll
            for (int half = 0; half < 2; half++) {
                int r = warp_m + mt * 16 + (lane >> 2) + half * 8;
                int grow = row0 + r;
                if (grow < ROWS) {
                    int bb = grow / T_;
                    int t  = grow % T_;
                    float2 val;
                    val.x = (acc[mt][nt][half * 2 + 0] + bv0) * scale;
                    val.y = (acc[mt][nt][half * 2 + 1] + bv1) * scale;
                    *(float2*)&out[(((size_t)(bb * H_ + h)) * T_ + t) * D_ + dd] = val;
                }
            }
        }
    }
}

// ---------------- output projection GEMM ----------------
__global__ __launch_bounds__(256, 2) void tf32_gemm_out(
    const float* __restrict__ bo, float* __restrict__ out)
{
    extern __shared__ float smem[];
    int row0 = blockIdx.y * BM;
    int col0 = blockIdx.x * BN;

    float acc[2][8][4];
    #pragma unroll
    for (int mt = 0; mt < 2; mt++)
        #pragma unroll
        for (int nt = 0; nt < 8; nt++)
            #pragma unroll
            for (int i = 0; i < 4; i++) acc[mt][nt][i] = 0.f;

    gemm_main(g_attn, g_w + (size_t)3 * WELEMS, row0, col0, acc, smem);

    int lane = threadIdx.x & 31;
    int wid  = threadIdx.x >> 5;
    int warp_m = (wid >> 1) * 32;
    int warp_n = (wid & 1) * 64;

    #pragma unroll
    for (int mt = 0; mt < 2; mt++) {
        #pragma unroll
        for (int nt = 0; nt < 8; nt++) {
            int coln = warp_n + nt * 8 + (lane & 3) * 2;
            int e = col0 + coln;
            float bv0 = bo[e];
            float bv1 = bo[e + 1];
            #pragma unroll
            for (int half = 0; half < 2; half++) {
                int r = warp_m + mt * 16 + (lane >> 2) + half * 8;
                int grow = row0 + r;
                if (grow < ROWS) {
                    float2 val;
                    val.x = acc[mt][nt][half * 2 + 0] + bv0;
                    val.y = acc[mt][nt][half * 2 + 1] + bv1;
                    *(float2*)&out[(size_t)grow * E_ + e] = val;
                }
            }
        }
    }
}

// ---------------- frame attention ----------------
__global__ __launch_bounds__(256) void frame_attn_kernel()
{
    int bx = blockIdx.x;
    int bh = bx / NF;
    int n  = bx % NF;
    int b  = bh / H_;
    int h  = bh % H_;

    extern __shared__ float smem[];
    float* Ks = smem;
    float* Vs = smem + 200 * D_;

    const float* kbase = g_k + (size_t)bh * T_ * D_;
    const float* vbase = g_v + (size_t)bh * T_ * D_;

    for (int idx = threadIdx.x; idx < 200 * 16; idx += 256) {
        int r  = idx / 16;
        int c4 = (idx % 16) * 4;
        int t  = (r < MCLS) ? r : (MCLS + n * LF + (r - MCLS));
        *(float4*)&Ks[r * D_ + c4] = *(const float4*)&kbase[(size_t)t * D_ + c4];
        *(float4*)&Vs[r * D_ + c4] = *(const float4*)&vbase[(size_t)t * D_ + c4];
    }
    __syncthreads();

    int l = threadIdx.x;
    if (l >= LF) return;
    int tq = MCLS + n * LF + l;

    const float* qrow = g_q + ((size_t)bh * T_ + tq) * D_;
    float4 q[16];
    #pragma unroll
    for (int i = 0; i < 16; i++) q[i] = *(const float4*)&qrow[i * 4];

    float m = -1e30f, lsum = 0.f;
    float4 acc[16];
    #pragma unroll
    for (int i = 0; i < 16; i++) acc[i] = make_float4(0.f, 0.f, 0.f, 0.f);

    for (int kk = 0; kk < 200; kk++) {
        const float* kr = &Ks[kk * D_];
        float s = 0.f;
        #pragma unroll
        for (int i = 0; i < 16; i++) {
            float4 kv = *(const float4*)&kr[i * 4];
            s += q[i].x * kv.x + q[i].y * kv.y + q[i].z * kv.z + q[i].w * kv.w;
        }
        float mnew = fmaxf(m, s);
        if (mnew != m) {
            float corr = __expf(m - mnew);
            lsum *= corr;
            #pragma unroll
            for (int i = 0; i < 16; i++) {
                acc[i].x *= corr; acc[i].y *= corr;
                acc[i].z *= corr; acc[i].w *= corr;
            }
            m = mnew;
        }
        float p = __expf(s - m);
        lsum += p;
        const float* vr = &Vs[kk * D_];
        #pragma unroll
        for (int i = 0; i < 16; i++) {
            float4 vv = *(const float4*)&vr[i * 4];
            acc[i].x += p * vv.x; acc[i].y += p * vv.y;
            acc[i].z += p * vv.z; acc[i].w += p * vv.w;
        }
    }

    float inv = 1.f / lsum;
    float* dst = g_attn + ((size_t)(b * T_ + tq)) * E_ + h * D_;
    #pragma unroll
    for (int i = 0; i < 16; i++) {
        float4 o;
        o.x = round_tf32(acc[i].x * inv);
        o.y = round_tf32(acc[i].y * inv);
        o.z = round_tf32(acc[i].z * inv);
        o.w = round_tf32(acc[i].w * inv);
        *(float4*)&dst[i * 4] = o;
    }
}

// ---------------- CLS attention ----------------
__global__ __launch_bounds__(128) void cls_attn_kernel()
{
    int bh   = blockIdx.x;
    int b    = bh / H_;
    int h    = bh % H_;
    int warp = threadIdx.x / 32;
    int lane = threadIdx.x % 32;

    const float* qrow = g_q + ((size_t)bh * T_ + warp) * D_;
    float4 q[16];
    #pragma unroll
    for (int i = 0; i < 16; i++) q[i] = *(const float4*)&qrow[i * 4];

    const float* kbase = g_k + (size_t)bh * T_ * D_;
    const float* vbase = g_v + (size_t)bh * T_ * D_;

    float m = -1e30f, lsum = 0.f;
    float4 acc[16];
    #pragma unroll
    for (int i = 0; i < 16; i++) acc[i] = make_float4(0.f, 0.f, 0.f, 0.f);

    for (int t = lane; t < T_; t += 32) {
        const float* kr = kbase + (size_t)t * D_;
        float s = 0.f;
        #pragma unroll
        for (int i = 0; i < 16; i++) {
            float4 kv = *(const float4*)&kr[i * 4];
            s += q[i].x * kv.x + q[i].y * kv.y + q[i].z * kv.z + q[i].w * kv.w;
        }
        float mnew = fmaxf(m, s);
        if (mnew != m) {
            float corr = __expf(m - mnew);
            lsum *= corr;
            #pragma unroll
            for (int i = 0; i < 16; i++) {
                acc[i].x *= corr; acc[i].y *= corr;
                acc[i].z *= corr; acc[i].w *= corr;
            }
            m = mnew;
        }
        float p = __expf(s - m);
        lsum += p;
        const float* vr = vbase + (size_t)t * D_;
        #pragma unroll
        for (int i = 0; i < 16; i++) {
            float4 vv = *(const float4*)&vr[i * 4];
            acc[i].x += p * vv.x; acc[i].y += p * vv.y;
            acc[i].z += p * vv.z; acc[i].w += p * vv.w;
        }
    }

    #pragma unroll
    for (int off = 16; off > 0; off >>= 1) {
        float m2 = __shfl_xor_sync(0xFFFFFFFFu, m, off);
        float l2 = __shfl_xor_sync(0xFFFFFFFFu, lsum, off);
        float mn = fmaxf(m, m2);
        float c1 = __expf(m - mn);
        float c2 = __expf(m2 - mn);
        lsum = lsum * c1 + l2 * c2;
        #pragma unroll
        for (int i = 0; i < 16; i++) {
            acc[i].x = acc[i].x * c1 + __shfl_xor_sync(0xFFFFFFFFu, acc[i].x, off) * c2;
            acc[i].y = acc[i].y * c1 + __shfl_xor_sync(0xFFFFFFFFu, acc[i].y, off) * c2;
            acc[i].z = acc[i].z * c1 + __shfl_xor_sync(0xFFFFFFFFu, acc[i].z, off) * c2;
            acc[i].w = acc[i].w * c1 + __shfl_xor_sync(0xFFFFFFFFu, acc[i].w, off) * c2;
        }
        m = mn;
    }

    float inv = 1.f / lsum;
    float* dst = g_attn + ((size_t)(b * T_ + warp)) * E_ + h * D_;
    if (lane < 16) {
        float4 o;
        o.x = round_tf32(acc[lane].x * inv);
        o.y = round_tf32(acc[lane].y * inv);
        o.z = round_tf32(acc[lane].z * inv);
        o.w = round_tf32(acc[lane].w * inv);
        *(float4*)&dst[lane * 4] = o;
    }
}

// ---------------- launch ----------------
extern "C" void kernel_launch(void* const* d_in, const int* in_sizes, int n_in,
                              void* d_out, int out_size)
{
    const float* hidden = (const float*)d_in[0];
    const float* Wq = (const float*)d_in[1];
    const float* bq = (const float*)d_in[2];
    const float* Wk = (const float*)d_in[3];
    const float* bk = (const float*)d_in[4];
    const float* Wv = (const float*)d_in[5];
    const float* bv = (const float*)d_in[6];
    const float* Wo = (const float*)d_in[7];
    const float* bo = (const float*)d_in[8];
    float* out = (float*)d_out;

    cudaFuncSetAttribute(tf32_gemm_qkv,
                         cudaFuncAttributeMaxDynamicSharedMemorySize, SMEM_BYTES);
    cudaFuncSetAttribute(tf32_gemm_out,
                         cudaFuncAttributeMaxDynamicSharedMemorySize, SMEM_BYTES);
    const int smem_attn = 2 * 200 * D_ * (int)sizeof(float);
    cudaFuncSetAttribute(frame_attn_kernel,
                         cudaFuncAttributeMaxDynamicSharedMemorySize, smem_attn);

    // prep: round inputs/weights to tf32
    {
        size_t n4 = ((size_t)ROWS * E_) / 4;
        prep_x_kernel<<<(unsigned)((n4 + 255) / 256), 256>>>(hidden);
        size_t w4 = ((size_t)4 * WELEMS) / 4;
        prep_w_kernel<<<(unsigned)((w4 + 255) / 256), 256>>>(Wq, Wk, Wv, Wo);
    }

    dim3 g1(E_ / BN, (ROWS + BM - 1) / BM, 3);
    tf32_gemm_qkv<<<g1, 256, SMEM_BYTES>>>(bq, bk, bv);

    frame_attn_kernel<<<B_ * H_ * NF, 256, smem_attn>>>();
    cls_attn_kernel<<<B_ * H_, 128>>>();

    dim3 g2(E_ / BN, (ROWS + BM - 1) / BM, 1);
    tf32_gemm_out<<<g2, 256, SMEM_BYTES>>>(bo, out);
}

// round 5
// speedup vs baseline: 3.2435x; 1.5145x over previous
#include <cuda_runtime.h>
#include <cuda_bf16.h>
#include <math.h>

// ---------------- problem constants ----------------
constexpr int B_   = 16;
constexpr int MCLS = 4;
constexpr int NF   = 12;
constexpr int LF   = 196;
constexpr int E_   = 768;
constexpr int H_   = 12;
constexpr int D_   = 64;
constexpr int T_   = MCLS + NF * LF;   // 2356
constexpr int ROWS = B_ * T_;          // 37696
constexpr float SCALE = 0.125f;
constexpr int WELEMS = E_ * E_;        // 589824

// ---------------- scratch ----------------
__device__ float g_q[(size_t)B_ * H_ * T_ * D_];
__device__ float g_k[(size_t)B_ * H_ * T_ * D_];
__device__ float g_v[(size_t)B_ * H_ * T_ * D_];
__device__ float g_attn[(size_t)B_ * T_ * E_];   // written pre-rounded to tf32
__device__ float g_x[(size_t)ROWS * E_];         // hidden, pre-rounded to tf32
__device__ float g_w[(size_t)4 * WELEMS];        // Wq,Wk,Wv,Wo pre-rounded

__device__ __forceinline__ float round_tf32(float x) {
    unsigned u;
    asm("cvt.rna.tf32.f32 %0, %1;" : "=r"(u) : "f"(x));
    return __uint_as_float(u);
}
__device__ __forceinline__ unsigned tf32u(float x) {
    unsigned u;
    asm("cvt.rna.tf32.f32 %0, %1;" : "=r"(u) : "f"(x));
    return u;
}

// ---------------- prep: round inputs/weights to tf32 once ----------------
__global__ __launch_bounds__(256) void prep_x_kernel(const float* __restrict__ X) {
    size_t i = ((size_t)blockIdx.x * 256 + threadIdx.x) * 4;
    if (i >= (size_t)ROWS * E_) return;
    float4 v = *(const float4*)&X[i];
    v.x = round_tf32(v.x); v.y = round_tf32(v.y);
    v.z = round_tf32(v.z); v.w = round_tf32(v.w);
    *(float4*)&g_x[i] = v;
}
__global__ __launch_bounds__(256) void prep_w_kernel(
    const float* __restrict__ Wq, const float* __restrict__ Wk,
    const float* __restrict__ Wv, const float* __restrict__ Wo) {
    size_t i = ((size_t)blockIdx.x * 256 + threadIdx.x) * 4;
    if (i >= (size_t)4 * WELEMS) return;
    int sel = (int)(i / WELEMS);
    size_t off = i - (size_t)sel * WELEMS;
    const float* W = (sel == 0) ? Wq : (sel == 1) ? Wk : (sel == 2) ? Wv : Wo;
    float4 v = *(const float4*)&W[off];
    v.x = round_tf32(v.x); v.y = round_tf32(v.y);
    v.z = round_tf32(v.z); v.w = round_tf32(v.w);
    *(float4*)&g_w[i] = v;
}

// ---------------- tf32 MMA GEMM config ----------------
constexpr int BM = 128;
constexpr int BN = 128;
constexpr int BKt = 32;
constexpr int AS_STRIDE = 36;
constexpr int BS_STRIDE = 136;
constexpr int AS_SIZE = BM * AS_STRIDE;
constexpr int BS_SIZE = BKt * BS_STRIDE;
constexpr int SMEM_BYTES = 2 * (AS_SIZE + BS_SIZE) * 4;  // 71680 B
constexpr int KTILES = E_ / BKt;

__device__ __forceinline__ void cp16(float* dst, const float* src, int srcsize) {
    unsigned s = (unsigned)__cvta_generic_to_shared(dst);
    asm volatile("cp.async.cg.shared.global [%0], [%1], 16, %2;\n"
                 :: "r"(s), "l"(src), "r"(srcsize));
}
__device__ __forceinline__ void mma_tf32(float c[4], const unsigned a[4], const unsigned b[2]) {
    asm volatile(
        "mma.sync.aligned.m16n8k8.row.col.f32.tf32.tf32.f32 "
        "{%0,%1,%2,%3},{%4,%5,%6,%7},{%8,%9},{%0,%1,%2,%3};\n"
        : "+f"(c[0]), "+f"(c[1]), "+f"(c[2]), "+f"(c[3])
        : "r"(a[0]), "r"(a[1]), "r"(a[2]), "r"(a[3]), "r"(b[0]), "r"(b[1]));
}

__device__ __forceinline__ void load_tile(
    const float* __restrict__ X, const float* __restrict__ W,
    float* As, float* Bs, int row0, int col0, int kt, int tid)
{
    int k0 = kt * BKt;
    #pragma unroll
    for (int i = 0; i < 4; i++) {
        int f  = tid + i * 256;
        int ar = f >> 3;
        int ac = (f & 7) * 4;
        int grow = row0 + ar;
        bool v = grow < ROWS;
        const float* src = X + (size_t)(v ? grow : 0) * E_ + k0 + ac;
        cp16(As + ar * AS_STRIDE + ac, src, v ? 16 : 0);
    }
    #pragma unroll
    for (int i = 0; i < 4; i++) {
        int f  = tid + i * 256;
        int br = f >> 5;
        int bc = (f & 31) * 4;
        cp16(Bs + br * BS_STRIDE + bc, W + (size_t)(k0 + br) * E_ + col0 + bc, 16);
    }
}

__device__ __forceinline__ void compute_tile(
    const float* As, const float* Bs,
    int warp_m, int warp_n, int lane, float acc[2][8][4])
{
    #pragma unroll
    for (int kk = 0; kk < BKt; kk += 8) {
        unsigned a[2][4], b[8][2];
        int cb = kk + (lane & 3);
        int g  = lane >> 2;
        #pragma unroll
        for (int mt = 0; mt < 2; mt++) {
            const unsigned* p = (const unsigned*)(As + (warp_m + mt * 16 + g) * AS_STRIDE + cb);
            a[mt][0] = p[0];
            a[mt][1] = p[8 * AS_STRIDE];
            a[mt][2] = p[4];
            a[mt][3] = p[8 * AS_STRIDE + 4];
        }
        const unsigned* q = (const unsigned*)(Bs + cb * BS_STRIDE + warp_n + g);
        #pragma unroll
        for (int nt = 0; nt < 8; nt++) {
            b[nt][0] = q[nt * 8];
            b[nt][1] = q[4 * BS_STRIDE + nt * 8];
        }
        #pragma unroll
        for (int mt = 0; mt < 2; mt++)
            #pragma unroll
            for (int nt = 0; nt < 8; nt++)
                mma_tf32(acc[mt][nt], a[mt], b[nt]);
    }
}

__device__ __forceinline__ void gemm_main(
    const float* __restrict__ X, const float* __restrict__ W,
    int row0, int col0, float acc[2][8][4], float* smem)
{
    float* As0 = smem;
    float* As1 = smem + AS_SIZE;
    float* Bs0 = smem + 2 * AS_SIZE;
    float* Bs1 = Bs0 + BS_SIZE;

    int tid  = threadIdx.x;
    int lane = tid & 31;
    int wid  = tid >> 5;
    int warp_m = (wid >> 1) * 32;
    int warp_n = (wid & 1) * 64;

    load_tile(X, W, As0, Bs0, row0, col0, 0, tid);
    asm volatile("cp.async.commit_group;\n" ::: "memory");

    for (int kt = 0; kt < KTILES; kt++) {
        float* Ac = (kt & 1) ? As1 : As0;
        float* Bc = (kt & 1) ? Bs1 : Bs0;
        if (kt + 1 < KTILES) {
            float* An = (kt & 1) ? As0 : As1;
            float* Bn = (kt & 1) ? Bs0 : Bs1;
            load_tile(X, W, An, Bn, row0, col0, kt + 1, tid);
            asm volatile("cp.async.commit_group;\n" ::: "memory");
            asm volatile("cp.async.wait_group 1;\n" ::: "memory");
        } else {
            asm volatile("cp.async.wait_group 0;\n" ::: "memory");
        }
        __syncthreads();
        compute_tile(Ac, Bc, warp_m, warp_n, lane, acc);
        __syncthreads();
    }
}

// ---------------- QKV GEMM ----------------
__global__ __launch_bounds__(256, 2) void tf32_gemm_qkv(
    const float* __restrict__ bq, const float* __restrict__ bk,
    const float* __restrict__ bv)
{
    extern __shared__ float smem[];
    int z = blockIdx.z;
    const float* W = g_w + (size_t)z * WELEMS;
    const float* bias = (z == 0) ? bq : (z == 1) ? bk : bv;
    float* out = (z == 0) ? g_q : (z == 1) ? g_k : g_v;
    float scale = (z == 0) ? SCALE : 1.0f;

    int row0 = blockIdx.y * BM;
    int col0 = blockIdx.x * BN;

    float acc[2][8][4];
    #pragma unroll
    for (int mt = 0; mt < 2; mt++)
        #pragma unroll
        for (int nt = 0; nt < 8; nt++)
            #pragma unroll
            for (int i = 0; i < 4; i++) acc[mt][nt][i] = 0.f;

    gemm_main(g_x, W, row0, col0, acc, smem);

    int lane = threadIdx.x & 31;
    int wid  = threadIdx.x >> 5;
    int warp_m = (wid >> 1) * 32;
    int warp_n = (wid & 1) * 64;

    #pragma unroll
    for (int mt = 0; mt < 2; mt++) {
        #pragma unroll
        for (int nt = 0; nt < 8; nt++) {
            int coln = warp_n + nt * 8 + (lane & 3) * 2;
            int e  = col0 + coln;
            int h  = e >> 6;
            int dd = e & 63;
            float bv0 = bias[e];
            float bv1 = bias[e + 1];
            #pragma unroll
            for (int half = 0; half < 2; half++) {
                int r = warp_m + mt * 16 + (lane >> 2) + half * 8;
                int grow = row0 + r;
                if (grow < ROWS) {
                    int bb = grow / T_;
                    int t  = grow % T_;
                    float2 val;
                    val.x = (acc[mt][nt][half * 2 + 0] + bv0) * scale;
                    val.y = (acc[mt][nt][half * 2 + 1] + bv1) * scale;
                    *(float2*)&out[(((size_t)(bb * H_ + h)) * T_ + t) * D_ + dd] = val;
                }
            }
        }
    }
}

// ---------------- output projection GEMM ----------------
__global__ __launch_bounds__(256, 2) void tf32_gemm_out(
    const float* __restrict__ bo, float* __restrict__ out)
{
    extern __shared__ float smem[];
    int row0 = blockIdx.y * BM;
    int col0 = blockIdx.x * BN;

    float acc[2][8][4];
    #pragma unroll
    for (int mt = 0; mt < 2; mt++)
        #pragma unroll
        for (int nt = 0; nt < 8; nt++)
            #pragma unroll
            for (int i = 0; i < 4; i++) acc[mt][nt][i] = 0.f;

    gemm_main(g_attn, g_w + (size_t)3 * WELEMS, row0, col0, acc, smem);

    int lane = threadIdx.x & 31;
    int wid  = threadIdx.x >> 5;
    int warp_m = (wid >> 1) * 32;
    int warp_n = (wid & 1) * 64;

    #pragma unroll
    for (int mt = 0; mt < 2; mt++) {
        #pragma unroll
        for (int nt = 0; nt < 8; nt++) {
            int coln = warp_n + nt * 8 + (lane & 3) * 2;
            int e = col0 + coln;
            float bv0 = bo[e];
            float bv1 = bo[e + 1];
            #pragma unroll
            for (int half = 0; half < 2; half++) {
                int r = warp_m + mt * 16 + (lane >> 2) + half * 8;
                int grow = row0 + r;
                if (grow < ROWS) {
                    float2 val;
                    val.x = acc[mt][nt][half * 2 + 0] + bv0;
                    val.y = acc[mt][nt][half * 2 + 1] + bv1;
                    *(float2*)&out[(size_t)grow * E_ + e] = val;
                }
            }
        }
    }
}

// ---------------- frame attention via tf32 MMA ----------------
// One block per (bh, window). 8 warps; m16-tiles of queries round-robin.
// Keys = 200 = 25 n8-tiles exactly. Queries 196 -> 13 m16-tiles (pad rows zeroed).
constexpr int FA_KSTR = 68;   // K smem row stride (4*17: conflict-free 8key x 4dim B-frag)
constexpr int FA_VSTR = 72;   // V smem row stride (8*9: conflict-free 4key x 8dim B-frag)
constexpr int FA_SSTR = 204;  // P scratch stride (4*51: conflict-free 8row x 4col A-frag)
constexpr int FA_NKT  = 25;   // key tiles (n8)
constexpr int FA_NMT  = 13;   // query tiles (m16)
constexpr int FA_SMEM = (200 * FA_KSTR + 200 * FA_VSTR + 8 * 16 * FA_SSTR) * 4; // 216448 B

__global__ __launch_bounds__(256) void frame_attn_mma_kernel()
{
    int bx = blockIdx.x;
    int bh = bx / NF;
    int n  = bx % NF;
    int b  = bh / H_;
    int h  = bh % H_;

    extern __shared__ float smem[];
    float* Ks = smem;                       // [200][FA_KSTR]
    float* Vs = Ks + 200 * FA_KSTR;         // [200][FA_VSTR]
    float* Ss = Vs + 200 * FA_VSTR;         // 8 x [16][FA_SSTR]

    int tid  = threadIdx.x;
    int lane = tid & 31;
    int wid  = tid >> 5;
    int g    = lane >> 2;   // row-group / n-group
    int c    = lane & 3;    // col-group / k-group

    const float* kbase = g_k + (size_t)bh * T_ * D_;
    const float* vbase = g_v + (size_t)bh * T_ * D_;

    // ---- stage K,V (tf32-rounded) ----
    for (int idx = tid; idx < 200 * 16; idx += 256) {
        int r  = idx >> 4;
        int c4 = (idx & 15) * 4;
        int t  = (r < MCLS) ? r : (MCLS + n * LF + (r - MCLS));
        float4 kv = *(const float4*)&kbase[(size_t)t * D_ + c4];
        float4 vv = *(const float4*)&vbase[(size_t)t * D_ + c4];
        kv.x = round_tf32(kv.x); kv.y = round_tf32(kv.y);
        kv.z = round_tf32(kv.z); kv.w = round_tf32(kv.w);
        vv.x = round_tf32(vv.x); vv.y = round_tf32(vv.y);
        vv.z = round_tf32(vv.z); vv.w = round_tf32(vv.w);
        *(float4*)&Ks[r * FA_KSTR + c4] = kv;
        *(float4*)&Vs[r * FA_VSTR + c4] = vv;
    }
    __syncthreads();

    const float* qbase = g_q + ((size_t)bh * T_ + MCLS + (size_t)n * LF) * D_;
    float* Sw = Ss + wid * 16 * FA_SSTR;

    for (int mt = wid; mt < FA_NMT; mt += 8) {
        int qr0 = mt * 16 + g;
        int qr1 = qr0 + 8;
        bool v0 = qr0 < LF;
        bool v1 = qr1 < LF;

        // Q fragments (tf32), zero for pad rows
        unsigned qa[8][4];
        #pragma unroll
        for (int kt = 0; kt < 8; kt++) {
            int col = kt * 8 + c;
            qa[kt][0] = v0 ? tf32u(qbase[(size_t)qr0 * D_ + col])     : 0u;
            qa[kt][1] = v1 ? tf32u(qbase[(size_t)qr1 * D_ + col])     : 0u;
            qa[kt][2] = v0 ? tf32u(qbase[(size_t)qr0 * D_ + col + 4]) : 0u;
            qa[kt][3] = v1 ? tf32u(qbase[(size_t)qr1 * D_ + col + 4]) : 0u;
        }

        // ---- S = Q K^T ----
        float sacc[FA_NKT][4];
        #pragma unroll
        for (int nt = 0; nt < FA_NKT; nt++)
            #pragma unroll
            for (int i = 0; i < 4; i++) sacc[nt][i] = 0.f;

        #pragma unroll
        for (int nt = 0; nt < FA_NKT; nt++) {
            const unsigned* kp = (const unsigned*)(Ks + (nt * 8 + g) * FA_KSTR + c);
            #pragma unroll
            for (int kt = 0; kt < 8; kt++) {
                unsigned bb[2];
                bb[0] = kp[kt * 8];
                bb[1] = kp[kt * 8 + 4];
                mma_tf32(sacc[nt], qa[kt], bb);
            }
        }

        // ---- softmax (row-wise over 200 cols) ----
        float mx0 = -1e30f, mx1 = -1e30f;
        #pragma unroll
        for (int nt = 0; nt < FA_NKT; nt++) {
            mx0 = fmaxf(mx0, fmaxf(sacc[nt][0], sacc[nt][1]));
            mx1 = fmaxf(mx1, fmaxf(sacc[nt][2], sacc[nt][3]));
        }
        mx0 = fmaxf(mx0, __shfl_xor_sync(0xFFFFFFFFu, mx0, 1));
        mx0 = fmaxf(mx0, __shfl_xor_sync(0xFFFFFFFFu, mx0, 2));
        mx1 = fmaxf(mx1, __shfl_xor_sync(0xFFFFFFFFu, mx1, 1));
        mx1 = fmaxf(mx1, __shfl_xor_sync(0xFFFFFFFFu, mx1, 2));

        float l0 = 0.f, l1 = 0.f;
        #pragma unroll
        for (int nt = 0; nt < FA_NKT; nt++) {
            sacc[nt][0] = __expf(sacc[nt][0] - mx0);
            sacc[nt][1] = __expf(sacc[nt][1] - mx0);
            sacc[nt][2] = __expf(sacc[nt][2] - mx1);
            sacc[nt][3] = __expf(sacc[nt][3] - mx1);
            l0 += sacc[nt][0] + sacc[nt][1];
            l1 += sacc[nt][2] + sacc[nt][3];
        }
        l0 += __shfl_xor_sync(0xFFFFFFFFu, l0, 1);
        l0 += __shfl_xor_sync(0xFFFFFFFFu, l0, 2);
        l1 += __shfl_xor_sync(0xFFFFFFFFu, l1, 1);
        l1 += __shfl_xor_sync(0xFFFFFFFFu, l1, 2);

        // store P (tf32) to warp scratch
        #pragma unroll
        for (int nt = 0; nt < FA_NKT; nt++) {
            int col = nt * 8 + c * 2;
            float2 p0, p1;
            p0.x = round_tf32(sacc[nt][0]); p0.y = round_tf32(sacc[nt][1]);
            p1.x = round_tf32(sacc[nt][2]); p1.y = round_tf32(sacc[nt][3]);
            *(float2*)&Sw[g * FA_SSTR + col]       = p0;
            *(float2*)&Sw[(g + 8) * FA_SSTR + col] = p1;
        }
        __syncwarp();

        // ---- O = P V ----
        float oacc[8][4];
        #pragma unroll
        for (int n2 = 0; n2 < 8; n2++)
            #pragma unroll
            for (int i = 0; i < 4; i++) oacc[n2][i] = 0.f;

        #pragma unroll
        for (int kt2 = 0; kt2 < FA_NKT; kt2++) {
            unsigned aa[4];
            aa[0] = __float_as_uint(Sw[g * FA_SSTR + kt2 * 8 + c]);
            aa[1] = __float_as_uint(Sw[(g + 8) * FA_SSTR + kt2 * 8 + c]);
            aa[2] = __float_as_uint(Sw[g * FA_SSTR + kt2 * 8 + c + 4]);
            aa[3] = __float_as_uint(Sw[(g + 8) * FA_SSTR + kt2 * 8 + c + 4]);
            const unsigned* vp0 = (const unsigned*)(Vs + (kt2 * 8 + c) * FA_VSTR + g);
            const unsigned* vp1 = (const unsigned*)(Vs + (kt2 * 8 + c + 4) * FA_VSTR + g);
            #pragma unroll
            for (int n2 = 0; n2 < 8; n2++) {
                unsigned bb[2];
                bb[0] = vp0[n2 * 8];
                bb[1] = vp1[n2 * 8];
                mma_tf32(oacc[n2], aa, bb);
            }
        }
        __syncwarp();

        // ---- normalize + store (tf32-rounded for output GEMM) ----
        float inv0 = 1.f / l0;
        float inv1 = 1.f / l1;
        #pragma unroll
        for (int n2 = 0; n2 < 8; n2++) {
            int d = n2 * 8 + c * 2;
            if (v0) {
                int tq = MCLS + n * LF + qr0;
                float2 o;
                o.x = round_tf32(oacc[n2][0] * inv0);
                o.y = round_tf32(oacc[n2][1] * inv0);
                *(float2*)&g_attn[((size_t)(b * T_ + tq)) * E_ + h * D_ + d] = o;
            }
            if (v1) {
                int tq = MCLS + n * LF + qr1;
                float2 o;
                o.x = round_tf32(oacc[n2][2] * inv1);
                o.y = round_tf32(oacc[n2][3] * inv1);
                *(float2*)&g_attn[((size_t)(b * T_ + tq)) * E_ + h * D_ + d] = o;
            }
        }
    }
}

// ---------------- CLS attention: one block per (bh, query) ----------------
__global__ __launch_bounds__(256) void cls_attn_kernel()
{
    int bx = blockIdx.x;
    int bh = bx >> 2;
    int qi = bx & 3;
    int b  = bh / H_;
    int h  = bh % H_;
    int tid  = threadIdx.x;
    int w    = tid >> 5;
    int lane = tid & 31;

    __shared__ float sm_m[8];
    __shared__ float sm_l[8];
    __shared__ float sm_acc[8][64];

    const float* qrow = g_q + ((size_t)bh * T_ + qi) * D_;
    float4 q[16];
    #pragma unroll
    for (int i = 0; i < 16; i++) q[i] = *(const float4*)&qrow[i * 4];

    const float* kbase = g_k + (size_t)bh * T_ * D_;
    const float* vbase = g_v + (size_t)bh * T_ * D_;

    float m = -1e30f, lsum = 0.f;
    float4 acc[16];
    #pragma unroll
    for (int i = 0; i < 16; i++) acc[i] = make_float4(0.f, 0.f, 0.f, 0.f);

    for (int t = tid; t < T_; t += 256) {
        const float* kr = kbase + (size_t)t * D_;
        float s = 0.f;
        #pragma unroll
        for (int i = 0; i < 16; i++) {
            float4 kv = *(const float4*)&kr[i * 4];
            s += q[i].x * kv.x + q[i].y * kv.y + q[i].z * kv.z + q[i].w * kv.w;
        }
        float mnew = fmaxf(m, s);
        if (mnew != m) {
            float corr = __expf(m - mnew);
            lsum *= corr;
            #pragma unroll
            for (int i = 0; i < 16; i++) {
                acc[i].x *= corr; acc[i].y *= corr;
                acc[i].z *= corr; acc[i].w *= corr;
            }
            m = mnew;
        }
        float p = __expf(s - m);
        lsum += p;
        const float* vr = vbase + (size_t)t * D_;
        #pragma unroll
        for (int i = 0; i < 16; i++) {
            float4 vv = *(const float4*)&vr[i * 4];
            acc[i].x += p * vv.x; acc[i].y += p * vv.y;
            acc[i].z += p * vv.z; acc[i].w += p * vv.w;
        }
    }

    // warp butterfly merge
    #pragma unroll
    for (int off = 16; off > 0; off >>= 1) {
        float m2 = __shfl_xor_sync(0xFFFFFFFFu, m, off);
        float l2 = __shfl_xor_sync(0xFFFFFFFFu, lsum, off);
        float mn = fmaxf(m, m2);
        float c1 = __expf(m - mn);
        float c2 = __expf(m2 - mn);
        lsum = lsum * c1 + l2 * c2;
        #pragma unroll
        for (int i = 0; i < 16; i++) {
            acc[i].x = acc[i].x * c1 + __shfl_xor_sync(0xFFFFFFFFu, acc[i].x, off) * c2;
            acc[i].y = acc[i].y * c1 + __shfl_xor_sync(0xFFFFFFFFu, acc[i].y, off) * c2;
            acc[i].z = acc[i].z * c1 + __shfl_xor_sync(0xFFFFFFFFu, acc[i].z, off) * c2;
            acc[i].w = acc[i].w * c1 + __shfl_xor_sync(0xFFFFFFFFu, acc[i].w, off) * c2;
        }
        m = mn;
    }

    if (lane == 0) { sm_m[w] = m; sm_l[w] = lsum; }
    if (lane < 16) *(float4*)&sm_acc[w][lane * 4] = acc[lane];
    __syncthreads();

    // cross-warp merge: first 64 threads, one dim each
    if (tid < 64) {
        float M = -1e30f;
        #pragma unroll
        for (int w2 = 0; w2 < 8; w2++) M = fmaxf(M, sm_m[w2]);
        float L = 0.f, o = 0.f;
        #pragma unroll
        for (int w2 = 0; w2 < 8; w2++) {
            float cc = __expf(sm_m[w2] - M);
            L += sm_l[w2] * cc;
            o += sm_acc[w2][tid] * cc;
        }
        g_attn[((size_t)(b * T_ + qi)) * E_ + h * D_ + tid] = round_tf32(o / L);
    }
}

// ---------------- launch ----------------
extern "C" void kernel_launch(void* const* d_in, const int* in_sizes, int n_in,
                              void* d_out, int out_size)
{
    const float* hidden = (const float*)d_in[0];
    const float* Wq = (const float*)d_in[1];
    const float* bq = (const float*)d_in[2];
    const float* Wk = (const float*)d_in[3];
    const float* bk = (const float*)d_in[4];
    const float* Wv = (const float*)d_in[5];
    const float* bv = (const float*)d_in[6];
    const float* Wo = (const float*)d_in[7];
    const float* bo = (const float*)d_in[8];
    float* out = (float*)d_out;

    cudaFuncSetAttribute(tf32_gemm_qkv,
                         cudaFuncAttributeMaxDynamicSharedMemorySize, SMEM_BYTES);
    cudaFuncSetAttribute(tf32_gemm_out,
                         cudaFuncAttributeMaxDynamicSharedMemorySize, SMEM_BYTES);
    cudaFuncSetAttribute(frame_attn_mma_kernel,
                         cudaFuncAttributeMaxDynamicSharedMemorySize, FA_SMEM);

    // prep: round inputs/weights to tf32
    {
        size_t n4 = ((size_t)ROWS * E_) / 4;
        prep_x_kernel<<<(unsigned)((n4 + 255) / 256), 256>>>(hidden);
        size_t w4 = ((size_t)4 * WELEMS) / 4;
        prep_w_kernel<<<(unsigned)((w4 + 255) / 256), 256>>>(Wq, Wk, Wv, Wo);
    }

    dim3 g1(E_ / BN, (ROWS + BM - 1) / BM, 3);
    tf32_gemm_qkv<<<g1, 256, SMEM_BYTES>>>(bq, bk, bv);

    frame_attn_mma_kernel<<<B_ * H_ * NF, 256, FA_SMEM>>>();
    cls_attn_kernel<<<B_ * H_ * MCLS, 256>>>();

    dim3 g2(E_ / BN, (ROWS + BM - 1) / BM, 1);
    tf32_gemm_out<<<g2, 256, SMEM_BYTES>>>(bo, out);
}

// round 7
// speedup vs baseline: 3.2543x; 1.0033x over previous
#include <cuda_runtime.h>
#include <cuda_bf16.h>
#include <math.h>

// ---------------- problem constants ----------------
constexpr int B_   = 16;
constexpr int MCLS = 4;
constexpr int NF   = 12;
constexpr int LF   = 196;
constexpr int E_   = 768;
constexpr int H_   = 12;
constexpr int D_   = 64;
constexpr int T_   = MCLS + NF * LF;   // 2356
constexpr int ROWS = B_ * T_;          // 37696
constexpr float SCALE = 0.125f;
constexpr int WELEMS = E_ * E_;        // 589824

// ---------------- scratch ----------------
__device__ float g_q[(size_t)B_ * H_ * T_ * D_];
__device__ float g_k[(size_t)B_ * H_ * T_ * D_];
__device__ float g_v[(size_t)B_ * H_ * T_ * D_];
__device__ float g_attn[(size_t)B_ * T_ * E_];   // written pre-rounded to tf32
__device__ float g_x[(size_t)ROWS * E_];         // hidden, pre-rounded to tf32
__device__ float g_w[(size_t)4 * WELEMS];        // Wq,Wk,Wv,Wo pre-rounded

__device__ __forceinline__ float round_tf32(float x) {
    unsigned u;
    asm("cvt.rna.tf32.f32 %0, %1;" : "=r"(u) : "f"(x));
    return __uint_as_float(u);
}
__device__ __forceinline__ unsigned tf32u(float x) {
    unsigned u;
    asm("cvt.rna.tf32.f32 %0, %1;" : "=r"(u) : "f"(x));
    return u;
}

// ---------------- prep: round inputs/weights to tf32 once ----------------
__global__ __launch_bounds__(256) void prep_x_kernel(const float* __restrict__ X) {
    size_t i = ((size_t)blockIdx.x * 256 + threadIdx.x) * 4;
    if (i >= (size_t)ROWS * E_) return;
    float4 v = *(const float4*)&X[i];
    v.x = round_tf32(v.x); v.y = round_tf32(v.y);
    v.z = round_tf32(v.z); v.w = round_tf32(v.w);
    *(float4*)&g_x[i] = v;
}
__global__ __launch_bounds__(256) void prep_w_kernel(
    const float* __restrict__ Wq, const float* __restrict__ Wk,
    const float* __restrict__ Wv, const float* __restrict__ Wo) {
    size_t i = ((size_t)blockIdx.x * 256 + threadIdx.x) * 4;
    if (i >= (size_t)4 * WELEMS) return;
    int sel = (int)(i / WELEMS);
    size_t off = i - (size_t)sel * WELEMS;
    const float* W = (sel == 0) ? Wq : (sel == 1) ? Wk : (sel == 2) ? Wv : Wo;
    float4 v = *(const float4*)&W[off];
    v.x = round_tf32(v.x); v.y = round_tf32(v.y);
    v.z = round_tf32(v.z); v.w = round_tf32(v.w);
    *(float4*)&g_w[i] = v;
}

// ---------------- tf32 MMA GEMM config (3-stage pipeline) ----------------
constexpr int BM = 128;
constexpr int BN = 128;
constexpr int BKt = 32;
constexpr int AS_STRIDE = 36;
constexpr int BS_STRIDE = 136;
constexpr int AS_SIZE = BM * AS_STRIDE;
constexpr int BS_SIZE = BKt * BS_STRIDE;
constexpr int STG_SIZE = AS_SIZE + BS_SIZE;           // floats per stage
constexpr int SMEM_BYTES = 3 * STG_SIZE * 4;          // 107520 B
constexpr int KTILES = E_ / BKt;                      // 24

__device__ __forceinline__ void cp16(float* dst, const float* src, int srcsize) {
    unsigned s = (unsigned)__cvta_generic_to_shared(dst);
    asm volatile("cp.async.cg.shared.global [%0], [%1], 16, %2;\n"
                 :: "r"(s), "l"(src), "r"(srcsize));
}
__device__ __forceinline__ void mma_tf32(float c[4], const unsigned a[4], const unsigned b[2]) {
    asm volatile(
        "mma.sync.aligned.m16n8k8.row.col.f32.tf32.tf32.f32 "
        "{%0,%1,%2,%3},{%4,%5,%6,%7},{%8,%9},{%0,%1,%2,%3};\n"
        : "+f"(c[0]), "+f"(c[1]), "+f"(c[2]), "+f"(c[3])
        : "r"(a[0]), "r"(a[1]), "r"(a[2]), "r"(a[3]), "r"(b[0]), "r"(b[1]));
}

__device__ __forceinline__ void load_tile(
    const float* __restrict__ X, const float* __restrict__ W,
    float* As, float* Bs, int row0, int col0, int kt, int tid)
{
    int k0 = kt * BKt;
    #pragma unroll
    for (int i = 0; i < 4; i++) {
        int f  = tid + i * 256;
        int ar = f >> 3;
        int ac = (f & 7) * 4;
        int grow = row0 + ar;
        bool v = grow < ROWS;
        const float* src = X + (size_t)(v ? grow : 0) * E_ + k0 + ac;
        cp16(As + ar * AS_STRIDE + ac, src, v ? 16 : 0);
    }
    #pragma unroll
    for (int i = 0; i < 4; i++) {
        int f  = tid + i * 256;
        int br = f >> 5;
        int bc = (f & 31) * 4;
        cp16(Bs + br * BS_STRIDE + bc, W + (size_t)(k0 + br) * E_ + col0 + bc, 16);
    }
}

__device__ __forceinline__ void compute_tile(
    const float* As, const float* Bs,
    int warp_m, int warp_n, int lane, float acc[2][8][4])
{
    #pragma unroll
    for (int kk = 0; kk < BKt; kk += 8) {
        unsigned a[2][4], b[8][2];
        int cb = kk + (lane & 3);
        int g  = lane >> 2;
        #pragma unroll
        for (int mt = 0; mt < 2; mt++) {
            const unsigned* p = (const unsigned*)(As + (warp_m + mt * 16 + g) * AS_STRIDE + cb);
            a[mt][0] = p[0];
            a[mt][1] = p[8 * AS_STRIDE];
            a[mt][2] = p[4];
            a[mt][3] = p[8 * AS_STRIDE + 4];
        }
        const unsigned* q = (const unsigned*)(Bs + cb * BS_STRIDE + warp_n + g);
        #pragma unroll
        for (int nt = 0; nt < 8; nt++) {
            b[nt][0] = q[nt * 8];
            b[nt][1] = q[4 * BS_STRIDE + nt * 8];
        }
        #pragma unroll
        for (int mt = 0; mt < 2; mt++)
            #pragma unroll
            for (int nt = 0; nt < 8; nt++)
                mma_tf32(acc[mt][nt], a[mt], b[nt]);
    }
}

__device__ __forceinline__ void gemm_main(
    const float* __restrict__ X, const float* __restrict__ W,
    int row0, int col0, float acc[2][8][4], float* smem)
{
    int tid  = threadIdx.x;
    int lane = tid & 31;
    int wid  = tid >> 5;
    int warp_m = (wid >> 1) * 32;
    int warp_n = (wid & 1) * 64;

    load_tile(X, W, smem, smem + AS_SIZE, row0, col0, 0, tid);
    asm volatile("cp.async.commit_group;\n" ::: "memory");
    load_tile(X, W, smem + STG_SIZE, smem + STG_SIZE + AS_SIZE, row0, col0, 1, tid);
    asm volatile("cp.async.commit_group;\n" ::: "memory");

    #pragma unroll 1
    for (int kt = 0; kt < KTILES; kt++) {
        float* cur = smem + (kt % 3) * STG_SIZE;
        if (kt + 2 < KTILES) {
            float* nxt = smem + ((kt + 2) % 3) * STG_SIZE;
            load_tile(X, W, nxt, nxt + AS_SIZE, row0, col0, kt + 2, tid);
            asm volatile("cp.async.commit_group;\n" ::: "memory");
            asm volatile("cp.async.wait_group 2;\n" ::: "memory");
        } else if (kt + 1 < KTILES) {
            asm volatile("cp.async.wait_group 1;\n" ::: "memory");
        } else {
            asm volatile("cp.async.wait_group 0;\n" ::: "memory");
        }
        __syncthreads();
        compute_tile(cur, cur + AS_SIZE, warp_m, warp_n, lane, acc);
        __syncthreads();
    }
}

// ---------------- QKV GEMM ----------------
__global__ __launch_bounds__(256, 2) void tf32_gemm_qkv(
    const float* __restrict__ bq, const float* __restrict__ bk,
    const float* __restrict__ bv)
{
    extern __shared__ float smem[];
    int z = blockIdx.z;
    const float* W = g_w + (size_t)z * WELEMS;
    const float* bias = (z == 0) ? bq : (z == 1) ? bk : bv;
    float* out = (z == 0) ? g_q : (z == 1) ? g_k : g_v;
    float scale = (z == 0) ? SCALE : 1.0f;

    int row0 = blockIdx.y * BM;
    int col0 = blockIdx.x * BN;

    float acc[2][8][4];
    #pragma unroll
    for (int mt = 0; mt < 2; mt++)
        #pragma unroll
        for (int nt = 0; nt < 8; nt++)
            #pragma unroll
            for (int i = 0; i < 4; i++) acc[mt][nt][i] = 0.f;

    gemm_main(g_x, W, row0, col0, acc, smem);

    int lane = threadIdx.x & 31;
    int wid  = threadIdx.x >> 5;
    int warp_m = (wid >> 1) * 32;
    int warp_n = (wid & 1) * 64;

    #pragma unroll
    for (int mt = 0; mt < 2; mt++) {
        #pragma unroll
        for (int nt = 0; nt < 8; nt++) {
            int coln = warp_n + nt * 8 + (lane & 3) * 2;
            int e  = col0 + coln;
            int h  = e >> 6;
            int dd = e & 63;
            float bv0 = bias[e];
            float bv1 = bias[e + 1];
            #pragma unroll
            for (int half = 0; half < 2; half++) {
                int r = warp_m + mt * 16 + (lane >> 2) + half * 8;
                int grow = row0 + r;
                if (grow < ROWS) {
                    int bb = grow / T_;
                    int t  = grow % T_;
                    float2 val;
                    val.x = (acc[mt][nt][half * 2 + 0] + bv0) * scale;
                    val.y = (acc[mt][nt][half * 2 + 1] + bv1) * scale;
                    *(float2*)&out[(((size_t)(bb * H_ + h)) * T_ + t) * D_ + dd] = val;
                }
            }
        }
    }
}

// ---------------- output projection GEMM ----------------
__global__ __launch_bounds__(256, 2) void tf32_gemm_out(
    const float* __restrict__ bo, float* __restrict__ out)
{
    extern __shared__ float smem[];
    int row0 = blockIdx.y * BM;
    int col0 = blockIdx.x * BN;

    float acc[2][8][4];
    #pragma unroll
    for (int mt = 0; mt < 2; mt++)
        #pragma unroll
        for (int nt = 0; nt < 8; nt++)
            #pragma unroll
            for (int i = 0; i < 4; i++) acc[mt][nt][i] = 0.f;

    gemm_main(g_attn, g_w + (size_t)3 * WELEMS, row0, col0, acc, smem);

    int lane = threadIdx.x & 31;
    int wid  = threadIdx.x >> 5;
    int warp_m = (wid >> 1) * 32;
    int warp_n = (wid & 1) * 64;

    #pragma unroll
    for (int mt = 0; mt < 2; mt++) {
        #pragma unroll
        for (int nt = 0; nt < 8; nt++) {
            int coln = warp_n + nt * 8 + (lane & 3) * 2;
            int e = col0 + coln;
            float bv0 = bo[e];
            float bv1 = bo[e + 1];
            #pragma unroll
            for (int half = 0; half < 2; half++) {
                int r = warp_m + mt * 16 + (lane >> 2) + half * 8;
                int grow = row0 + r;
                if (grow < ROWS) {
                    float2 val;
                    val.x = acc[mt][nt][half * 2 + 0] + bv0;
                    val.y = acc[mt][nt][half * 2 + 1] + bv1;
                    *(float2*)&out[(size_t)grow * E_ + e] = val;
                }
            }
        }
    }
}

// ---------------- frame attention via tf32 MMA, 2 m-tiles/warp + key chunks ----------------
constexpr int FA_KSTR = 68;   // K smem stride (conflict-free B-frag loads)
constexpr int FA_VSTR = 72;   // V smem stride (conflict-free B-frag loads)
constexpr int FA_SWSTR = 44;  // P scratch stride (conflict-free A-frag loads)
constexpr int FA_CH  = 5;     // k-tiles per chunk
constexpr int FA_NCH = 5;     // chunks (25 key tiles)
constexpr int FA_SMEM = (200 * FA_KSTR + 200 * FA_VSTR + 8 * 32 * FA_SWSTR) * 4; // 157056

__global__ __launch_bounds__(256) void frame_attn_mma_kernel()
{
    int bx = blockIdx.x;
    int bh = bx / NF;
    int n  = bx % NF;
    int b  = bh / H_;
    int h  = bh % H_;

    extern __shared__ float smem[];
    float* Ks = smem;                       // [200][FA_KSTR]
    float* Vs = Ks + 200 * FA_KSTR;         // [200][FA_VSTR]
    float* Ss = Vs + 200 * FA_VSTR;         // 8 x [32][FA_SWSTR]

    int tid  = threadIdx.x;
    int lane = tid & 31;
    int wid  = tid >> 5;
    int g    = lane >> 2;
    int c    = lane & 3;

    const float* kbase = g_k + (size_t)bh * T_ * D_;
    const float* vbase = g_v + (size_t)bh * T_ * D_;

    // ---- stage K,V (tf32-rounded) ----
    for (int idx = tid; idx < 200 * 16; idx += 256) {
        int r  = idx >> 4;
        int c4 = (idx & 15) * 4;
        int t  = (r < MCLS) ? r : (MCLS + n * LF + (r - MCLS));
        float4 kv = *(const float4*)&kbase[(size_t)t * D_ + c4];
        float4 vv = *(const float4*)&vbase[(size_t)t * D_ + c4];
        kv.x = round_tf32(kv.x); kv.y = round_tf32(kv.y);
        kv.z = round_tf32(kv.z); kv.w = round_tf32(kv.w);
        vv.x = round_tf32(vv.x); vv.y = round_tf32(vv.y);
        vv.z = round_tf32(vv.z); vv.w = round_tf32(vv.w);
        *(float4*)&Ks[r * FA_KSTR + c4] = kv;
        *(float4*)&Vs[r * FA_VSTR + c4] = vv;
    }
    __syncthreads();

    if (wid >= 7) return;   // warps 0..6 cover 7*32=224 >= 196 rows; no block syncs below

    const float* qbase = g_q + ((size_t)bh * T_ + MCLS + (size_t)n * LF) * D_;
    float* Sw = Ss + wid * 32 * FA_SWSTR;

    int m0 = wid * 32;
    int r0 = m0 + g;          // mt0 upper
    int r1 = m0 + 8 + g;      // mt0 lower
    int r2 = m0 + 16 + g;     // mt1 upper
    int r3 = m0 + 24 + g;     // mt1 lower
    bool v0 = r0 < LF, v1 = r1 < LF, v2 = r2 < LF, v3 = r3 < LF;

    // Q fragments for both m-tiles (zero for pad rows)
    unsigned qa[2][8][4];
    #pragma unroll
    for (int kt = 0; kt < 8; kt++) {
        int col = kt * 8 + c;
        qa[0][kt][0] = v0 ? tf32u(qbase[(size_t)r0 * D_ + col])     : 0u;
        qa[0][kt][1] = v1 ? tf32u(qbase[(size_t)r1 * D_ + col])     : 0u;
        qa[0][kt][2] = v0 ? tf32u(qbase[(size_t)r0 * D_ + col + 4]) : 0u;
        qa[0][kt][3] = v1 ? tf32u(qbase[(size_t)r1 * D_ + col + 4]) : 0u;
        qa[1][kt][0] = v2 ? tf32u(qbase[(size_t)r2 * D_ + col])     : 0u;
        qa[1][kt][1] = v3 ? tf32u(qbase[(size_t)r3 * D_ + col])     : 0u;
        qa[1][kt][2] = v2 ? tf32u(qbase[(size_t)r2 * D_ + col + 4]) : 0u;
        qa[1][kt][3] = v3 ? tf32u(qbase[(size_t)r3 * D_ + col + 4]) : 0u;
    }

    float mrow[4] = {-1e30f, -1e30f, -1e30f, -1e30f};
    float lrow[4] = {0.f, 0.f, 0.f, 0.f};
    float oacc[2][8][4];
    #pragma unroll
    for (int mt = 0; mt < 2; mt++)
        #pragma unroll
        for (int n2 = 0; n2 < 8; n2++)
            #pragma unroll
            for (int i = 0; i < 4; i++) oacc[mt][n2][i] = 0.f;

    #pragma unroll 1
    for (int ch = 0; ch < FA_NCH; ch++) {
        // ---- S chunk = Q K^T (keys ch*40 .. ch*40+39) ----
        float sacc[2][FA_CH][4];
        #pragma unroll
        for (int mt = 0; mt < 2; mt++)
            #pragma unroll
            for (int nt = 0; nt < FA_CH; nt++)
                #pragma unroll
                for (int i = 0; i < 4; i++) sacc[mt][nt][i] = 0.f;

        #pragma unroll
        for (int nt = 0; nt < FA_CH; nt++) {
            int ntg = ch * FA_CH + nt;
            const unsigned* kp = (const unsigned*)(Ks + (ntg * 8 + g) * FA_KSTR + c);
            #pragma unroll
            for (int kt = 0; kt < 8; kt++) {
                unsigned bb[2];
                bb[0] = kp[kt * 8];
                bb[1] = kp[kt * 8 + 4];
                mma_tf32(sacc[0][nt], qa[0][kt], bb);
                mma_tf32(sacc[1][nt], qa[1][kt], bb);
            }
        }

        // ---- online softmax update per m-tile ----
        #pragma unroll
        for (int mt = 0; mt < 2; mt++) {
            float cm0 = -1e30f, cm1 = -1e30f;
            #pragma unroll
            for (int nt = 0; nt < FA_CH; nt++) {
                cm0 = fmaxf(cm0, fmaxf(sacc[mt][nt][0], sacc[mt][nt][1]));
                cm1 = fmaxf(cm1, fmaxf(sacc[mt][nt][2], sacc[mt][nt][3]));
            }
            cm0 = fmaxf(cm0, __shfl_xor_sync(0xFFFFFFFFu, cm0, 1));
            cm0 = fmaxf(cm0, __shfl_xor_sync(0xFFFFFFFFu, cm0, 2));
            cm1 = fmaxf(cm1, __shfl_xor_sync(0xFFFFFFFFu, cm1, 1));
            cm1 = fmaxf(cm1, __shfl_xor_sync(0xFFFFFFFFu, cm1, 2));

            float mn0 = fmaxf(mrow[2 * mt + 0], cm0);
            float mn1 = fmaxf(mrow[2 * mt + 1], cm1);
            float corr0 = __expf(mrow[2 * mt + 0] - mn0);
            float corr1 = __expf(mrow[2 * mt + 1] - mn1);
            mrow[2 * mt + 0] = mn0;
            mrow[2 * mt + 1] = mn1;

            float rs0 = 0.f, rs1 = 0.f;
            #pragma unroll
            for (int nt = 0; nt < FA_CH; nt++) {
                sacc[mt][nt][0] = __expf(sacc[mt][nt][0] - mn0);
                sacc[mt][nt][1] = __expf(sacc[mt][nt][1] - mn0);
                sacc[mt][nt][2] = __expf(sacc[mt][nt][2] - mn1);
                sacc[mt][nt][3] = __expf(sacc[mt][nt][3] - mn1);
                rs0 += sacc[mt][nt][0] + sacc[mt][nt][1];
                rs1 += sacc[mt][nt][2] + sacc[mt][nt][3];
            }
            rs0 += __shfl_xor_sync(0xFFFFFFFFu, rs0, 1);
            rs0 += __shfl_xor_sync(0xFFFFFFFFu, rs0, 2);
            rs1 += __shfl_xor_sync(0xFFFFFFFFu, rs1, 1);
            rs1 += __shfl_xor_sync(0xFFFFFFFFu, rs1, 2);

            lrow[2 * mt + 0] = lrow[2 * mt + 0] * corr0 + rs0;
            lrow[2 * mt + 1] = lrow[2 * mt + 1] * corr1 + rs1;

            #pragma unroll
            for (int n2 = 0; n2 < 8; n2++) {
                oacc[mt][n2][0] *= corr0; oacc[mt][n2][1] *= corr0;
                oacc[mt][n2][2] *= corr1; oacc[mt][n2][3] *= corr1;
            }

            // store P chunk (tf32) to warp scratch
            #pragma unroll
            for (int nt = 0; nt < FA_CH; nt++) {
                int col = nt * 8 + 2 * c;
                float2 p0, p1;
                p0.x = round_tf32(sacc[mt][nt][0]); p0.y = round_tf32(sacc[mt][nt][1]);
                p1.x = round_tf32(sacc[mt][nt][2]); p1.y = round_tf32(sacc[mt][nt][3]);
                *(float2*)&Sw[(mt * 16 + g) * FA_SWSTR + col]     = p0;
                *(float2*)&Sw[(mt * 16 + 8 + g) * FA_SWSTR + col] = p1;
            }
        }
        __syncwarp();

        // ---- O += P V (chunk) ----
        #pragma unroll
        for (int kt2 = 0; kt2 < FA_CH; kt2++) {
            unsigned aa[2][4];
            #pragma unroll
            for (int mt = 0; mt < 2; mt++) {
                aa[mt][0] = __float_as_uint(Sw[(mt * 16 + g) * FA_SWSTR + kt2 * 8 + c]);
                aa[mt][1] = __float_as_uint(Sw[(mt * 16 + 8 + g) * FA_SWSTR + kt2 * 8 + c]);
                aa[mt][2] = __float_as_uint(Sw[(mt * 16 + g) * FA_SWSTR + kt2 * 8 + c + 4]);
                aa[mt][3] = __float_as_uint(Sw[(mt * 16 + 8 + g) * FA_SWSTR + kt2 * 8 + c + 4]);
            }
            int key0 = ch * (FA_CH * 8) + kt2 * 8 + c;
            const unsigned* vp0 = (const unsigned*)(Vs + key0 * FA_VSTR + g);
            const unsigned* vp1 = (const unsigned*)(Vs + (key0 + 4) * FA_VSTR + g);
            #pragma unroll
            for (int n2 = 0; n2 < 8; n2++) {
                unsigned bb[2];
                bb[0] = vp0[n2 * 8];
                bb[1] = vp1[n2 * 8];
                mma_tf32(oacc[0][n2], aa[0], bb);
                mma_tf32(oacc[1][n2], aa[1], bb);
            }
        }
        __syncwarp();
    }

    // ---- normalize + store (tf32-rounded for output GEMM) ----
    float inv0 = 1.f / lrow[0];
    float inv1 = 1.f / lrow[1];
    float inv2 = 1.f / lrow[2];
    float inv3 = 1.f / lrow[3];
    #pragma unroll
    for (int n2 = 0; n2 < 8; n2++) {
        int d = n2 * 8 + 2 * c;
        if (v0) {
            int tq = MCLS + n * LF + r0;
            float2 o;
            o.x = round_tf32(oacc[0][n2][0] * inv0);
            o.y = round_tf32(oacc[0][n2][1] * inv0);
            *(float2*)&g_attn[((size_t)(b * T_ + tq)) * E_ + h * D_ + d] = o;
        }
        if (v1) {
            int tq = MCLS + n * LF + r1;
            float2 o;
            o.x = round_tf32(oacc[0][n2][2] * inv1);
            o.y = round_tf32(oacc[0][n2][3] * inv1);
            *(float2*)&g_attn[((size_t)(b * T_ + tq)) * E_ + h * D_ + d] = o;
        }
        if (v2) {
            int tq = MCLS + n * LF + r2;
            float2 o;
            o.x = round_tf32(oacc[1][n2][0] * inv2);
            o.y = round_tf32(oacc[1][n2][1] * inv2);
            *(float2*)&g_attn[((size_t)(b * T_ + tq)) * E_ + h * D_ + d] = o;
        }
        if (v3) {
            int tq = MCLS + n * LF + r3;
            float2 o;
            o.x = round_tf32(oacc[1][n2][2] * inv3);
            o.y = round_tf32(oacc[1][n2][3] * inv3);
            *(float2*)&g_attn[((size_t)(b * T_ + tq)) * E_ + h * D_ + d] = o;
        }
    }
}

// ---------------- CLS attention: one block per (bh, query) ----------------
__global__ __launch_bounds__(256) void cls_attn_kernel()
{
    int bx = blockIdx.x;
    int bh = bx >> 2;
    int qi = bx & 3;
    int b  = bh / H_;
    int h  = bh % H_;
    int tid  = threadIdx.x;
    int w    = tid >> 5;
    int lane = tid & 31;

    __shared__ float sm_m[8];
    __shared__ float sm_l[8];
    __shared__ float sm_acc[8][64];

    const float* qrow = g_q + ((size_t)bh * T_ + qi) * D_;
    float4 q[16];
    #pragma unroll
    for (int i = 0; i < 16; i++) q[i] = *(const float4*)&qrow[i * 4];

    const float* kbase = g_k + (size_t)bh * T_ * D_;
    const float* vbase = g_v + (size_t)bh * T_ * D_;

    float m = -1e30f, lsum = 0.f;
    float4 acc[16];
    #pragma unroll
    for (int i = 0; i < 16; i++) acc[i] = make_float4(0.f, 0.f, 0.f, 0.f);

    for (int t = tid; t < T_; t += 256) {
        const float* kr = kbase + (size_t)t * D_;
        float s = 0.f;
        #pragma unroll
        for (int i = 0; i < 16; i++) {
            float4 kv = *(const float4*)&kr[i * 4];
            s += q[i].x * kv.x + q[i].y * kv.y + q[i].z * kv.z + q[i].w * kv.w;
        }
        float mnew = fmaxf(m, s);
        if (mnew != m) {
            float corr = __expf(m - mnew);
            lsum *= corr;
            #pragma unroll
            for (int i = 0; i < 16; i++) {
                acc[i].x *= corr; acc[i].y *= corr;
                acc[i].z *= corr; acc[i].w *= corr;
            }
            m = mnew;
        }
        float p = __expf(s - m);
        lsum += p;
        const float* vr = vbase + (size_t)t * D_;
        #pragma unroll
        for (int i = 0; i < 16; i++) {
            float4 vv = *(const float4*)&vr[i * 4];
            acc[i].x += p * vv.x; acc[i].y += p * vv.y;
            acc[i].z += p * vv.z; acc[i].w += p * vv.w;
        }
    }

    #pragma unroll
    for (int off = 16; off > 0; off >>= 1) {
        float m2 = __shfl_xor_sync(0xFFFFFFFFu, m, off);
        float l2 = __shfl_xor_sync(0xFFFFFFFFu, lsum, off);
        float mn = fmaxf(m, m2);
        float c1 = __expf(m - mn);
        float c2 = __expf(m2 - mn);
        lsum = lsum * c1 + l2 * c2;
        #pragma unroll
        for (int i = 0; i < 16; i++) {
            acc[i].x = acc[i].x * c1 + __shfl_xor_sync(0xFFFFFFFFu, acc[i].x, off) * c2;
            acc[i].y = acc[i].y * c1 + __shfl_xor_sync(0xFFFFFFFFu, acc[i].y, off) * c2;
            acc[i].z = acc[i].z * c1 + __shfl_xor_sync(0xFFFFFFFFu, acc[i].z, off) * c2;
            acc[i].w = acc[i].w * c1 + __shfl_xor_sync(0xFFFFFFFFu, acc[i].w, off) * c2;
        }
        m = mn;
    }

    if (lane == 0) { sm_m[w] = m; sm_l[w] = lsum; }
    if (lane < 16) *(float4*)&sm_acc[w][lane * 4] = acc[lane];
    __syncthreads();

    if (tid < 64) {
        float M = -1e30f;
        #pragma unroll
        for (int w2 = 0; w2 < 8; w2++) M = fmaxf(M, sm_m[w2]);
        float L = 0.f, o = 0.f;
        #pragma unroll
        for (int w2 = 0; w2 < 8; w2++) {
            float cc = __expf(sm_m[w2] - M);
            L += sm_l[w2] * cc;
            o += sm_acc[w2][tid] * cc;
        }
        g_attn[((size_t)(b * T_ + qi)) * E_ + h * D_ + tid] = round_tf32(o / L);
    }
}

// ---------------- launch ----------------
extern "C" void kernel_launch(void* const* d_in, const int* in_sizes, int n_in,
                              void* d_out, int out_size)
{
    const float* hidden = (const float*)d_in[0];
    const float* Wq = (const float*)d_in[1];
    const float* bq = (const float*)d_in[2];
    const float* Wk = (const float*)d_in[3];
    const float* bk = (const float*)d_in[4];
    const float* Wv = (const float*)d_in[5];
    const float* bv = (const float*)d_in[6];
    const float* Wo = (const float*)d_in[7];
    const float* bo = (const float*)d_in[8];
    float* out = (float*)d_out;

    cudaFuncSetAttribute(tf32_gemm_qkv,
                         cudaFuncAttributeMaxDynamicSharedMemorySize, SMEM_BYTES);
    cudaFuncSetAttribute(tf32_gemm_out,
                         cudaFuncAttributeMaxDynamicSharedMemorySize, SMEM_BYTES);
    cudaFuncSetAttribute(frame_attn_mma_kernel,
                         cudaFuncAttributeMaxDynamicSharedMemorySize, FA_SMEM);

    {
        size_t n4 = ((size_t)ROWS * E_) / 4;
        prep_x_kernel<<<(unsigned)((n4 + 255) / 256), 256>>>(hidden);
        size_t w4 = ((size_t)4 * WELEMS) / 4;
        prep_w_kernel<<<(unsigned)((w4 + 255) / 256), 256>>>(Wq, Wk, Wv, Wo);
    }

    dim3 g1(E_ / BN, (ROWS + BM - 1) / BM, 3);
    tf32_gemm_qkv<<<g1, 256, SMEM_BYTES>>>(bq, bk, bv);

    frame_attn_mma_kernel<<<B_ * H_ * NF, 256, FA_SMEM>>>();
    cls_attn_kernel<<<B_ * H_ * MCLS, 256>>>();

    dim3 g2(E_ / BN, (ROWS + BM - 1) / BM, 1);
    tf32_gemm_out<<<g2, 256, SMEM_BYTES>>>(bo, out);
}